// round 4
// baseline (speedup 1.0000x reference)
#include <cuda_runtime.h>
#include <math.h>

#define NPT   8192
#define CC    128
#define PP    1024
#define KMAX  64
#define KT    32      // neighbor tile for the attn GEMM
#define PSTR  68      // preT row stride (floats): 68*4=272 B, 16B-aligned, conflict-free STS.128

// scratch (device globals; no allocations allowed)
__device__ float g_Asrc[NPT*CC];
__device__ float g_Adst[NPT*CC];
__device__ float g_V[NPT*CC];
__device__ int   g_idx[NPT*KMAX];
__device__ int   g_cnt[NPT];

__device__ __forceinline__ void fma2(unsigned long long& acc,
                                     unsigned long long a,
                                     unsigned long long b)
{
    asm("fma.rn.f32x2 %0, %1, %2, %0;" : "+l"(acc) : "l"(a), "l"(b));
}
__device__ __forceinline__ unsigned long long splat2(float w)
{
    unsigned long long w2;
    asm("mov.b64 %0, {%1, %1};" : "=l"(w2) : "f"(w));
    return w2;
}
__device__ __forceinline__ void unpack2(unsigned long long v, float& lo, float& hi)
{
    asm("mov.b64 {%0, %1}, %2;" : "=f"(lo), "=f"(hi) : "l"(v));
}

// ---------------------------------------------------------------------------
// Kernel A: three GEMMs  x[8192,128] @ {w_lin,w_src,w_dst}[128,128]  (f32x2)
// grid (512, 3), block 128.  16 rows per block, transposed x tile in smem.
// ---------------------------------------------------------------------------
__global__ __launch_bounds__(128)
void gemm3_kernel(const float* __restrict__ x,
                  const float* __restrict__ w_lin,
                  const float* __restrict__ w_src,
                  const float* __restrict__ w_dst)
{
    const int c    = threadIdx.x;
    const int row0 = blockIdx.x * 16;

    const float* W; float* O;
    if (blockIdx.y == 0)      { W = w_lin; O = g_V;    }
    else if (blockIdx.y == 1) { W = w_src; O = g_Asrc; }
    else                      { W = w_dst; O = g_Adst; }

    // xs[r][ii] = x[row0+ii][r], stride 20 floats (80B, 16B-aligned)
    __shared__ __align__(16) float xs[128 * 20];
    #pragma unroll
    for (int ii = 0; ii < 16; ii++)
        xs[c * 20 + ii] = x[(row0 + ii) * CC + c];
    __syncthreads();

    unsigned long long acc[8];
    #pragma unroll
    for (int p = 0; p < 8; p++) acc[p] = 0ull;

    const float* wc = W + c;
    #pragma unroll 4
    for (int r = 0; r < 128; r++) {
        unsigned long long w2 = splat2(wc[r * CC]);
        const ulonglong2* xr = (const ulonglong2*)(xs + r * 20);
        #pragma unroll
        for (int p4 = 0; p4 < 4; p4++) {
            ulonglong2 a = xr[p4];
            fma2(acc[2 * p4],     a.x, w2);
            fma2(acc[2 * p4 + 1], a.y, w2);
        }
    }
    #pragma unroll
    for (int p = 0; p < 8; p++) {
        float lo, hi;
        unpack2(acc[p], lo, hi);
        O[(row0 + 2 * p) * CC + c]     = lo;
        O[(row0 + 2 * p + 1) * CC + c] = hi;
    }
}

// ---------------------------------------------------------------------------
// Kernel B: radius + nearest-K selection. 4 targets per block, cloud staged
// in smem. Effective set = { j : d2 <= min(64th smallest d2, R^2) }.
// Deterministic ordered compaction (ascending j) via ballot prefix sums.
// ---------------------------------------------------------------------------
__global__ __launch_bounds__(128)
void neigh_kernel(const float* __restrict__ pos)
{
    const int t     = threadIdx.x;
    const int lane  = t & 31;
    const int wid   = t >> 5;
    const int i0    = blockIdx.x * 4;
    const int cbase = (i0 >> 10) << 10;

    __shared__ float pos_s[PP * 3];     // 12 KB
    __shared__ int   red[4];

    for (int idx = t; idx < PP * 3; idx += 128)
        pos_s[idx] = pos[cbase * 3 + idx];
    __syncthreads();

    const unsigned R2b = __float_as_uint(0.04f);

    for (int tt = 0; tt < 4; tt++) {
        const int i  = i0 + tt;
        const int li = i - cbase;
        const float px = pos_s[li * 3 + 0];
        const float py = pos_s[li * 3 + 1];
        const float pz = pos_s[li * 3 + 2];

        unsigned bits[8];
        #pragma unroll
        for (int q = 0; q < 8; q++) {
            int j = q * 128 + t;
            float dx = px - pos_s[j * 3 + 0];
            float dy = py - pos_s[j * 3 + 1];
            float dz = pz - pos_s[j * 3 + 2];
            float d2 = dx * dx + dy * dy + dz * dz;
            bits[q] = __float_as_uint(d2);   // >=0 floats: bit order == value order
        }

        // count within radius
        int local = 0;
        #pragma unroll
        for (int q = 0; q < 8; q++) local += (bits[q] <= R2b);
        #pragma unroll
        for (int o = 16; o > 0; o >>= 1) local += __shfl_down_sync(0xffffffffu, local, o);
        if (lane == 0) red[wid] = local;
        __syncthreads();
        int total = red[0] + red[1] + red[2] + red[3];
        __syncthreads();

        unsigned th = R2b;
        if (total > KMAX) {
            unsigned lo = 0, hi = R2b;
            while (lo < hi) {
                unsigned mid = lo + ((hi - lo) >> 1);
                int cnt = 0;
                #pragma unroll
                for (int q = 0; q < 8; q++) cnt += (bits[q] <= mid);
                #pragma unroll
                for (int o = 16; o > 0; o >>= 1) cnt += __shfl_down_sync(0xffffffffu, cnt, o);
                if (lane == 0) red[wid] = cnt;
                __syncthreads();
                int tot = red[0] + red[1] + red[2] + red[3];
                __syncthreads();
                if (tot >= KMAX) hi = mid; else lo = mid + 1;
            }
            th = lo;
        }

        // ordered compaction: j ascending over (q, t)
        int wbase = 0;
        for (int q = 0; q < 8; q++) {
            bool sel = (bits[q] <= th);
            unsigned ball = __ballot_sync(0xffffffffu, sel);
            if (lane == 0) red[wid] = __popc(ball);
            __syncthreads();
            int woff = 0;
            #pragma unroll
            for (int w = 0; w < 4; w++) if (w < wid) woff += red[w];
            int tot = red[0] + red[1] + red[2] + red[3];
            int rank = wbase + woff + __popc(ball & ((1u << lane) - 1u));
            if (sel && rank < KMAX) g_idx[i * KMAX + rank] = q * 128 + t;
            wbase += tot;
            __syncthreads();
        }
        if (t == 0) g_cnt[i] = (wbase < KMAX) ? wbase : KMAX;
        __syncthreads();
    }
}

// ---------------------------------------------------------------------------
// Kernel C: fused delta / attention GEMM (f32x2) / softmax / aggregate.
// One block per target, 128 threads (thread == output channel).
// pre stored TRANSPOSED in smem: preT[r=cin][k], so neighbor pairs are
// contiguous 8B lanes for fma.rn.f32x2. GEMM loads are warp-uniform
// broadcasts; phase-1 STS.128 is conflict-free (stride 68 -> 17c+k/4 mod 8).
// ---------------------------------------------------------------------------
__global__ __launch_bounds__(128)
void main_kernel(const float* __restrict__ pos,
                 const float* __restrict__ nrm,
                 const float* __restrict__ w_pos,
                 const float* __restrict__ b_pos,
                 const float* __restrict__ pos_gamma,
                 const float* __restrict__ pos_beta,
                 const float* __restrict__ pos_mean,
                 const float* __restrict__ pos_var,
                 const float* __restrict__ w_attn,
                 const float* __restrict__ b_attn,
                 const float* __restrict__ attn_gamma,
                 const float* __restrict__ attn_beta,
                 const float* __restrict__ attn_mean,
                 const float* __restrict__ attn_var,
                 float* __restrict__ out)
{
    __shared__ __align__(16) float preT[CC * PSTR];   // ~34 KB
    __shared__ __align__(16) float rel_s[KMAX * 8];   //  2 KB
    __shared__ int   idx_s[KMAX];
    __shared__ float pi6[6];

    const int i     = blockIdx.x;
    const int c     = threadIdx.x;
    const int cbase = (i >> 10) << 10;
    const int m     = g_cnt[i];

    if (c < 6)    pi6[c]   = (c < 3) ? pos[i * 3 + c] : nrm[i * 3 + c - 3];
    if (c < KMAX) idx_s[c] = (c < m) ? g_idx[i * KMAX + c] : 0;
    __syncthreads();

    if (c < KMAX && c < m) {
        int gj = cbase + idx_s[c];
        rel_s[c * 8 + 0] = pi6[0] - pos[gj * 3 + 0];
        rel_s[c * 8 + 1] = pi6[1] - pos[gj * 3 + 1];
        rel_s[c * 8 + 2] = pi6[2] - pos[gj * 3 + 2];
        rel_s[c * 8 + 3] = pi6[3] - nrm[gj * 3 + 0];
        rel_s[c * 8 + 4] = pi6[4] - nrm[gj * 3 + 1];
        rel_s[c * 8 + 5] = pi6[5] - nrm[gj * 3 + 2];
    }

    // fold BatchNorms into per-channel affines
    const float sp = rsqrtf(pos_var[c]  + 1e-5f) * pos_gamma[c];
    const float bp = (b_pos[c]  - pos_mean[c])  * sp + pos_beta[c];
    const float sa = rsqrtf(attn_var[c] + 1e-5f) * attn_gamma[c];
    const float ba = (b_attn[c] - attn_mean[c]) * sa + attn_beta[c];
    float wpf[6];
    #pragma unroll
    for (int r = 0; r < 6; r++) wpf[r] = w_pos[r * CC + c] * sp;
    const float ad = g_Adst[i * CC + c];

    const int ntile = (m + KT - 1) / KT;   // 1 or 2
    const int mpad  = ntile * KT;
    __syncthreads();                        // rel_s ready

    // phase 1: thread c fills its own row preT[c][0..mpad)
    {
        float* rowp = &preT[c * PSTR];
        for (int k0 = 0; k0 < mpad; k0 += 4) {
            float vv[4];
            #pragma unroll
            for (int j = 0; j < 4; j++) {
                int k = k0 + j;
                float val = 0.f;
                if (k < m) {
                    const float* rl = &rel_s[k * 8];
                    float d = bp;
                    #pragma unroll
                    for (int r = 0; r < 6; r++) d = fmaf(rl[r], wpf[r], d);
                    d = fmaxf(d, 0.f);
                    int gj = cbase + idx_s[k];
                    val = ad - g_Asrc[(size_t)gj * CC + c] + d;
                }
                vv[j] = val;
            }
            *(float4*)(rowp + k0) = make_float4(vv[0], vv[1], vv[2], vv[3]);
        }
    }
    __syncthreads();

    float fsum = 0.f, facc = 0.f;
    const float* wc = w_attn + c;

    for (int kt = 0; kt < ntile; kt++) {
        const int kb = kt * KT;
        unsigned long long acc[16];
        #pragma unroll
        for (int p = 0; p < 16; p++) acc[p] = 0ull;

        #pragma unroll 2
        for (int r = 0; r < 128; r++) {
            unsigned long long w2 = splat2(wc[r * CC]);
            const ulonglong2* ps = (const ulonglong2*)(preT + r * PSTR + kb);
            #pragma unroll
            for (int p4 = 0; p4 < 8; p4++) {
                ulonglong2 a = ps[p4];
                fma2(acc[2 * p4],     a.x, w2);
                fma2(acc[2 * p4 + 1], a.y, w2);
            }
        }

        // epilogue: affine+relu, exp (alpha>=0 so no max-subtraction needed),
        // recompute delta from rel_s, gather V, accumulate softmax.
        #pragma unroll
        for (int p = 0; p < 16; p++) {
            float a0, a1;
            unpack2(acc[p], a0, a1);
            #pragma unroll
            for (int h = 0; h < 2; h++) {
                int k = kb + 2 * p + h;
                float av = h ? a1 : a0;
                if (k < m) {
                    float alpha = fmaxf(fmaf(av, sa, ba), 0.f);
                    float e = __expf(alpha);
                    const float* rl = &rel_s[k * 8];
                    float d = bp;
                    #pragma unroll
                    for (int r = 0; r < 6; r++) d = fmaf(rl[r], wpf[r], d);
                    d = fmaxf(d, 0.f);
                    int gj = cbase + idx_s[k];
                    fsum += e;
                    facc = fmaf(e, g_V[(size_t)gj * CC + c] + d, facc);
                }
            }
        }
    }
    out[i * CC + c] = facc / fsum;
}

// ---------------------------------------------------------------------------
extern "C" void kernel_launch(void* const* d_in, const int* in_sizes, int n_in,
                              void* d_out, int out_size)
{
    const float* x      = (const float*)d_in[0];
    const float* pos    = (const float*)d_in[1];
    const float* nrm    = (const float*)d_in[2];
    // d_in[3] = batch (structured, unused)
    const float* w_lin  = (const float*)d_in[4];
    const float* w_src  = (const float*)d_in[5];
    const float* w_dst  = (const float*)d_in[6];
    const float* w_pos  = (const float*)d_in[7];
    const float* b_pos  = (const float*)d_in[8];
    const float* pos_g  = (const float*)d_in[9];
    const float* pos_b  = (const float*)d_in[10];
    const float* pos_m  = (const float*)d_in[11];
    const float* pos_v  = (const float*)d_in[12];
    const float* w_attn = (const float*)d_in[13];
    const float* b_attn = (const float*)d_in[14];
    const float* attn_g = (const float*)d_in[15];
    const float* attn_b = (const float*)d_in[16];
    const float* attn_m = (const float*)d_in[17];
    const float* attn_v = (const float*)d_in[18];
    float* out = (float*)d_out;

    gemm3_kernel<<<dim3(512, 3, 1), 128>>>(x, w_lin, w_src, w_dst);
    neigh_kernel<<<NPT / 4, 128>>>(pos);
    main_kernel<<<NPT, 128>>>(pos, nrm, w_pos, b_pos, pos_g, pos_b, pos_m, pos_v,
                              w_attn, b_attn, attn_g, attn_b, attn_m, attn_v, out);
}

// round 6
// speedup vs baseline: 1.2316x; 1.2316x over previous
#include <cuda_runtime.h>
#include <cuda_fp16.h>
#include <math.h>

#define NPT   8192
#define CC    128
#define PP    1024
#define KMAX  64
#define NPAIR (NPT/2)
#define GRID_MAIN 296

#define ASTR_B 272          // A/BT row stride in bytes (136 halves)

// dynamic smem layout (byte offsets)
#define OFF_A    0          // A: 128 x 272B = 34816 ; eS (32KB) overlays after MMA
#define OFF_B    34816      // BT: 128 x 272B = 34816
#define OFF_REL  69632      // 128*8 floats = 4096
#define OFF_IDX  73728      // 128 ints = 512
#define OFF_RED  74240      // 512 floats = 2048
#define OFF_WPF  76288      // 6*128 floats = 3072
#define OFF_BP   79360      // 128 floats
#define OFF_SA   79872
#define OFF_BA   80384
#define OFF_M    80896      // 2 ints
#define DYN_SIZE 81920

// scratch (device globals; no allocations allowed)
__device__ float g_Asrc[NPT*CC];
__device__ float g_Adst[NPT*CC];
__device__ float g_V[NPT*CC];
__device__ int   g_idx[NPT*KMAX];
__device__ int   g_cnt[NPT];

// ---------------------------------------------------------------------------
__device__ __forceinline__ unsigned smem_u32(const void* p) {
    unsigned a;
    asm("{ .reg .u64 t; cvta.to.shared.u64 t, %1; cvt.u32.u64 %0, t; }" : "=r"(a) : "l"(p));
    return a;
}

__device__ __forceinline__ void ldsm4(unsigned* r, unsigned addr) {
    asm volatile("ldmatrix.sync.aligned.m8n8.x4.shared.b16 {%0,%1,%2,%3}, [%4];"
        : "=r"(r[0]), "=r"(r[1]), "=r"(r[2]), "=r"(r[3]) : "r"(addr));
}

__device__ __forceinline__ void mma16816(float* d, const unsigned* a, unsigned b0, unsigned b1) {
    asm volatile("mma.sync.aligned.m16n8k16.row.col.f32.f16.f16.f32 "
        "{%0,%1,%2,%3}, {%4,%5,%6,%7}, {%8,%9}, {%0,%1,%2,%3};"
        : "+f"(d[0]), "+f"(d[1]), "+f"(d[2]), "+f"(d[3])
        : "r"(a[0]), "r"(a[1]), "r"(a[2]), "r"(a[3]), "r"(b0), "r"(b1));
}

// XOR-swizzled eS addressing (float index), 128 rows x 64 cols
__device__ __forceinline__ int eaddr(int r, int cl) {
    return (r << 6) + (cl & 32) + ((cl ^ r) & 31);
}

// ---------------------------------------------------------------------------
// Kernel C: HMMA fused attention. Persistent, 2 targets per iteration.
// ---------------------------------------------------------------------------
__global__ __launch_bounds__(256, 2)
void main_tc_kernel(const float* __restrict__ pos,
                    const float* __restrict__ nrm,
                    const float* __restrict__ w_pos,
                    const float* __restrict__ b_pos,
                    const float* __restrict__ pos_gamma,
                    const float* __restrict__ pos_beta,
                    const float* __restrict__ pos_mean,
                    const float* __restrict__ pos_var,
                    const float* __restrict__ w_attn,
                    const float* __restrict__ b_attn,
                    const float* __restrict__ attn_gamma,
                    const float* __restrict__ attn_beta,
                    const float* __restrict__ attn_mean,
                    const float* __restrict__ attn_var,
                    float* __restrict__ out)
{
    extern __shared__ __align__(16) char smem[];
    const unsigned sb = smem_u32(smem);

    const int t    = threadIdx.x;
    const int w    = t >> 5;
    const int lane = t & 31;

    float* eS   = (float*)(smem + OFF_A);     // overlays A after MMA
    float* relS = (float*)(smem + OFF_REL);
    int*   idxS = (int*)  (smem + OFF_IDX);
    float* redS = (float*)(smem + OFF_RED);
    float* wpfS = (float*)(smem + OFF_WPF);
    float* bpS  = (float*)(smem + OFF_BP);
    float* saS  = (float*)(smem + OFF_SA);
    float* baS  = (float*)(smem + OFF_BA);
    int*   mS   = (int*)  (smem + OFF_M);

    // per-channel folded-BN constants
    if (t < 128) {
        int c = t;
        float sp = rsqrtf(pos_var[c] + 1e-5f) * pos_gamma[c];
        bpS[c] = (b_pos[c] - pos_mean[c]) * sp + pos_beta[c];
        #pragma unroll
        for (int r = 0; r < 6; r++) wpfS[r * 128 + c] = w_pos[r * 128 + c] * sp;
        float sa = rsqrtf(attn_var[c] + 1e-5f) * attn_gamma[c];
        saS[c] = sa;
        baS[c] = (b_attn[c] - attn_mean[c]) * sa + attn_beta[c];
    }

    // BT[n][k] = w_attn[k][n] as fp16, row stride 136 halves (once per CTA)
    for (int q = t; q < 128 * 128; q += 256) {
        int n = q & 127, k = q >> 7;
        *(__half*)(smem + OFF_B + n * ASTR_B + k * 2) = __float2half_rn(w_attn[k * 128 + n]);
    }
    __syncthreads();

    for (int p = blockIdx.x; p < NPAIR; p += GRID_MAIN) {
        const int i0 = 2 * p;
        __syncthreads();   // prev-iter epilogue done (eS/rel/idx reuse)

        // --- neighbor metadata: rel6, idx, m for both targets ---
        if (t < 2) mS[t] = g_cnt[i0 + t];
        if (t < 128) {
            int tgt = t >> 6, k = t & 63;
            int i = i0 + tgt;
            int m = g_cnt[i];
            int cb = (i >> 10) << 10;
            int jj = (k < m) ? g_idx[i * KMAX + k] : 0;
            idxS[t] = jj;
            int gj = cb + jj;
            float r0 = 0, r1 = 0, r2 = 0, r3 = 0, r4 = 0, r5 = 0;
            if (k < m) {
                r0 = pos[i * 3 + 0] - pos[gj * 3 + 0];
                r1 = pos[i * 3 + 1] - pos[gj * 3 + 1];
                r2 = pos[i * 3 + 2] - pos[gj * 3 + 2];
                r3 = nrm[i * 3 + 0] - nrm[gj * 3 + 0];
                r4 = nrm[i * 3 + 1] - nrm[gj * 3 + 1];
                r5 = nrm[i * 3 + 2] - nrm[gj * 3 + 2];
            }
            relS[t * 8 + 0] = r0; relS[t * 8 + 1] = r1; relS[t * 8 + 2] = r2;
            relS[t * 8 + 3] = r3; relS[t * 8 + 4] = r4; relS[t * 8 + 5] = r5;
        }
        __syncthreads();

        // --- build A: pre[row = tgt*64 + k][col = cin] fp16 (real rows only) ---
        {
            int tgt = t >> 7;
            int c   = t & 127;
            int i   = i0 + tgt;
            int cb  = (i >> 10) << 10;
            int mt  = mS[tgt];
            int tb  = tgt * 64;
            float ad = g_Adst[i * CC + c];
            float bp = bpS[c];
            float wp0 = wpfS[0 * 128 + c], wp1 = wpfS[1 * 128 + c], wp2 = wpfS[2 * 128 + c];
            float wp3 = wpfS[3 * 128 + c], wp4 = wpfS[4 * 128 + c], wp5 = wpfS[5 * 128 + c];

            float buf[4];
            #pragma unroll
            for (int kp = 0; kp < 4; kp++)
                buf[kp] = (kp < mt) ? g_Asrc[(size_t)(cb + idxS[tb + kp]) * CC + c] : 0.f;

            for (int k = 0; k < mt; k++) {
                float as = buf[k & 3];
                if (k + 4 < mt) buf[k & 3] = g_Asrc[(size_t)(cb + idxS[tb + k + 4]) * CC + c];
                const float* rl = &relS[(tb + k) * 8];
                float d = bp;
                d = fmaf(rl[0], wp0, d); d = fmaf(rl[1], wp1, d); d = fmaf(rl[2], wp2, d);
                d = fmaf(rl[3], wp3, d); d = fmaf(rl[4], wp4, d); d = fmaf(rl[5], wp5, d);
                d = fmaxf(d, 0.f);
                float val = ad - as + d;
                *(__half*)(smem + OFF_A + (tb + k) * ASTR_B + c * 2) = __float2half_rn(val);
            }
        }
        __syncthreads();

        // --- HMMA: warp w computes rows [w*16, w*16+16) x all 128 couts ---
        float acc[16][4];
        #pragma unroll
        for (int nt = 0; nt < 16; nt++) {
            acc[nt][0] = 0.f; acc[nt][1] = 0.f; acc[nt][2] = 0.f; acc[nt][3] = 0.f;
        }
        {
            const unsigned aBase = sb + OFF_A +
                (unsigned)((w * 16 + (lane & 15)) * ASTR_B + ((lane >> 4) << 4));
            const unsigned bBase = sb + OFF_B +
                (unsigned)((((lane >> 4) << 3) + (lane & 7)) * ASTR_B + (((lane >> 3) & 1) << 4));

            for (int kk = 0; kk < 8; kk++) {
                unsigned afr[4];
                ldsm4(afr, aBase + kk * 32);
                #pragma unroll
                for (int pp = 0; pp < 8; pp++) {
                    unsigned bfr[4];
                    ldsm4(bfr, bBase + (unsigned)(pp * 16 * ASTR_B) + kk * 32);
                    mma16816(acc[2 * pp],     afr, bfr[0], bfr[1]);
                    mma16816(acc[2 * pp + 1], afr, bfr[2], bfr[3]);
                }
            }
        }
        __syncthreads();   // all warps done reading A -> eS may overlay it

        // --- epilogue: 2 halves of 64 couts each ---
        for (int cc = 0; cc < 2; cc++) {
            // store this half's alphas (pre-affine) to eS
            {
                int r0 = w * 16 + (lane >> 2);
                int c0 = 2 * (lane & 3);
                #pragma unroll
                for (int ntl = 0; ntl < 8; ntl++) {
                    int nt = cc * 8 + ntl;
                    int cl = ntl * 8 + c0;
                    eS[eaddr(r0,     cl)]     = acc[nt][0];
                    eS[eaddr(r0,     cl + 1)] = acc[nt][1];
                    eS[eaddr(r0 + 8, cl)]     = acc[nt][2];
                    eS[eaddr(r0 + 8, cl + 1)] = acc[nt][3];
                }
            }
            __syncthreads();

            // aggregate: thread -> (kgroup g = t>>6, local cout cl = t&63)
            {
                int cl  = t & 63;
                int g   = t >> 6;
                int tgt = g >> 1;
                int i   = i0 + tgt;
                int cb  = (i >> 10) << 10;
                int mt  = mS[tgt];
                int cp  = cc * 64 + cl;
                float sa = saS[cp], ba = baS[cp], bp = bpS[cp];
                float wp[6];
                #pragma unroll
                for (int r6 = 0; r6 < 6; r6++) wp[r6] = wpfS[r6 * 128 + cp];
                int rowb = g << 5;
                int klb  = (g & 1) << 5;
                int ibase = tgt * 64;

                float vbuf[4];
                #pragma unroll
                for (int kp = 0; kp < 4; kp++) {
                    int kl = klb + kp;
                    vbuf[kp] = (kl < mt) ? g_V[(size_t)(cb + idxS[ibase + kl]) * CC + cp] : 0.f;
                }

                float fs = 0.f, fa = 0.f;
                for (int j = 0; j < 32; j++) {
                    int kl = klb + j;
                    if (kl < mt) {
                        float v = vbuf[j & 3];
                        if (kl + 4 < mt)
                            vbuf[j & 3] = g_V[(size_t)(cb + idxS[ibase + kl + 4]) * CC + cp];
                        const float* rl = &relS[(ibase + kl) * 8];
                        float d = bp;
                        d = fmaf(rl[0], wp[0], d); d = fmaf(rl[1], wp[1], d);
                        d = fmaf(rl[2], wp[2], d); d = fmaf(rl[3], wp[3], d);
                        d = fmaf(rl[4], wp[4], d); d = fmaf(rl[5], wp[5], d);
                        d = fmaxf(d, 0.f);
                        float alpha = fmaxf(fmaf(eS[eaddr(rowb + j, cl)], sa, ba), 0.f);
                        float e = __expf(alpha);
                        fs += e;
                        fa = fmaf(e, v + d, fa);
                    }
                }
                redS[(g * 64 + cl) * 2 + 0] = fs;
                redS[(g * 64 + cl) * 2 + 1] = fa;
            }
            __syncthreads();

            if (t < 128) {
                int tgt = t >> 6, cl = t & 63;
                int cp = cc * 64 + cl;
                int g0 = tgt * 2;
                float den = redS[(g0 * 64 + cl) * 2 + 0] + redS[((g0 + 1) * 64 + cl) * 2 + 0];
                float num = redS[(g0 * 64 + cl) * 2 + 1] + redS[((g0 + 1) * 64 + cl) * 2 + 1];
                out[(size_t)(i0 + tgt) * CC + cp] = num / den;
            }
            if (cc == 0) __syncthreads();   // eS reads done before half-1 overwrites
        }
    }
}

// ---------------------------------------------------------------------------
// Kernel A: three GEMMs  x[8192,128] @ {w_lin,w_src,w_dst}  (fp32)
// ---------------------------------------------------------------------------
__global__ __launch_bounds__(128)
void gemm3_kernel(const float* __restrict__ x,
                  const float* __restrict__ w_lin,
                  const float* __restrict__ w_src,
                  const float* __restrict__ w_dst)
{
    const int c    = threadIdx.x;
    const int row0 = blockIdx.x * 16;

    const float* W; float* O;
    if (blockIdx.y == 0)      { W = w_lin; O = g_V;    }
    else if (blockIdx.y == 1) { W = w_src; O = g_Asrc; }
    else                      { W = w_dst; O = g_Adst; }

    __shared__ __align__(16) float xs[128 * 20];
    #pragma unroll
    for (int ii = 0; ii < 16; ii++)
        xs[c * 20 + ii] = x[(row0 + ii) * CC + c];
    __syncthreads();

    float acc[16];
    #pragma unroll
    for (int q = 0; q < 16; q++) acc[q] = 0.f;

    const float* wc = W + c;
    #pragma unroll 4
    for (int r = 0; r < 128; r++) {
        float wv = wc[r * CC];
        const float* xr = &xs[r * 20];
        #pragma unroll
        for (int q = 0; q < 16; q += 4) {
            float4 pq = *(const float4*)(xr + q);
            acc[q]     = fmaf(pq.x, wv, acc[q]);
            acc[q + 1] = fmaf(pq.y, wv, acc[q + 1]);
            acc[q + 2] = fmaf(pq.z, wv, acc[q + 2]);
            acc[q + 3] = fmaf(pq.w, wv, acc[q + 3]);
        }
    }
    #pragma unroll
    for (int ii = 0; ii < 16; ii++)
        O[(row0 + ii) * CC + c] = acc[ii];
}

// ---------------------------------------------------------------------------
// Kernel B: radius + nearest-K selection (smem-staged cloud)
// ---------------------------------------------------------------------------
__global__ __launch_bounds__(128)
void neigh_kernel(const float* __restrict__ pos)
{
    const int t     = threadIdx.x;
    const int lane  = t & 31;
    const int wid   = t >> 5;
    const int i0    = blockIdx.x * 4;
    const int cbase = (i0 >> 10) << 10;

    __shared__ float pos_s[PP * 3];
    __shared__ int   red[4];

    for (int idx = t; idx < PP * 3; idx += 128)
        pos_s[idx] = pos[cbase * 3 + idx];
    __syncthreads();

    const unsigned R2b = __float_as_uint(0.04f);

    for (int tt = 0; tt < 4; tt++) {
        const int i  = i0 + tt;
        const int li = i - cbase;
        const float px = pos_s[li * 3 + 0];
        const float py = pos_s[li * 3 + 1];
        const float pz = pos_s[li * 3 + 2];

        unsigned bits[8];
        #pragma unroll
        for (int q = 0; q < 8; q++) {
            int j = q * 128 + t;
            float dx = px - pos_s[j * 3 + 0];
            float dy = py - pos_s[j * 3 + 1];
            float dz = pz - pos_s[j * 3 + 2];
            float d2 = dx * dx + dy * dy + dz * dz;
            bits[q] = __float_as_uint(d2);   // >=0 floats: bit order == value order
        }

        int local = 0;
        #pragma unroll
        for (int q = 0; q < 8; q++) local += (bits[q] <= R2b);
        #pragma unroll
        for (int o = 16; o > 0; o >>= 1) local += __shfl_down_sync(0xffffffffu, local, o);
        if (lane == 0) red[wid] = local;
        __syncthreads();
        int total = red[0] + red[1] + red[2] + red[3];
        __syncthreads();

        unsigned th = R2b;
        if (total > KMAX) {
            unsigned lo = 0, hi = R2b;
            while (lo < hi) {
                unsigned mid = lo + ((hi - lo) >> 1);
                int cnt = 0;
                #pragma unroll
                for (int q = 0; q < 8; q++) cnt += (bits[q] <= mid);
                #pragma unroll
                for (int o = 16; o > 0; o >>= 1) cnt += __shfl_down_sync(0xffffffffu, cnt, o);
                if (lane == 0) red[wid] = cnt;
                __syncthreads();
                int tot = red[0] + red[1] + red[2] + red[3];
                __syncthreads();
                if (tot >= KMAX) hi = mid; else lo = mid + 1;
            }
            th = lo;
        }

        int wbase = 0;
        for (int q = 0; q < 8; q++) {
            bool sel = (bits[q] <= th);
            unsigned ball = __ballot_sync(0xffffffffu, sel);
            if (lane == 0) red[wid] = __popc(ball);
            __syncthreads();
            int woff = 0;
            #pragma unroll
            for (int ww = 0; ww < 4; ww++) if (ww < wid) woff += red[ww];
            int tot = red[0] + red[1] + red[2] + red[3];
            int rank = wbase + woff + __popc(ball & ((1u << lane) - 1u));
            if (sel && rank < KMAX) g_idx[i * KMAX + rank] = q * 128 + t;
            wbase += tot;
            __syncthreads();
        }
        if (t == 0) g_cnt[i] = (wbase < KMAX) ? wbase : KMAX;
        __syncthreads();
    }
}

// ---------------------------------------------------------------------------
extern "C" void kernel_launch(void* const* d_in, const int* in_sizes, int n_in,
                              void* d_out, int out_size)
{
    const float* x      = (const float*)d_in[0];
    const float* pos    = (const float*)d_in[1];
    const float* nrm    = (const float*)d_in[2];
    // d_in[3] = batch (structured, unused)
    const float* w_lin  = (const float*)d_in[4];
    const float* w_src  = (const float*)d_in[5];
    const float* w_dst  = (const float*)d_in[6];
    const float* w_pos  = (const float*)d_in[7];
    const float* b_pos  = (const float*)d_in[8];
    const float* pos_g  = (const float*)d_in[9];
    const float* pos_b  = (const float*)d_in[10];
    const float* pos_m  = (const float*)d_in[11];
    const float* pos_v  = (const float*)d_in[12];
    const float* w_attn = (const float*)d_in[13];
    const float* b_attn = (const float*)d_in[14];
    const float* attn_g = (const float*)d_in[15];
    const float* attn_b = (const float*)d_in[16];
    const float* attn_m = (const float*)d_in[17];
    const float* attn_v = (const float*)d_in[18];
    float* out = (float*)d_out;

    cudaFuncSetAttribute(main_tc_kernel,
                         cudaFuncAttributeMaxDynamicSharedMemorySize, DYN_SIZE);

    gemm3_kernel<<<dim3(512, 3, 1), 128>>>(x, w_lin, w_src, w_dst);
    neigh_kernel<<<NPT / 4, 128>>>(pos);
    main_tc_kernel<<<GRID_MAIN, 256, DYN_SIZE>>>(
        pos, nrm, w_pos, b_pos, pos_g, pos_b, pos_m, pos_v,
        w_attn, b_attn, attn_g, attn_b, attn_m, attn_v, out);
}

// round 8
// speedup vs baseline: 2.1256x; 1.7258x over previous
#include <cuda_runtime.h>
#include <cuda_fp16.h>
#include <math.h>

#define NPT   8192
#define CC    128
#define PP    1024
#define KMAX  64
#define NPAIR (NPT/2)
#define GRID_MAIN 296

#define ASTR_B 272          // A/BT row stride in bytes (136 halves)

// main kernel dynamic smem layout (byte offsets)
#define OFF_A    0          // A: 128 x 272B = 34816 ; eS (32KB) overlays after MMA
#define OFF_B    34816      // BT: 128 x 272B = 34816
#define OFF_REL  69632      // 128*8 floats = 4096
#define OFF_IDX  73728      // 128 ints = 512
#define OFF_RED  74240      // 512 floats = 2048
#define OFF_WPF  76288      // 6*128 floats = 3072
#define OFF_BP   79360      // 128 floats
#define OFF_SA   79872
#define OFF_BA   80384
#define OFF_M    80896      // 2 ints
#define DYN_SIZE 81920

// gemm3 dynamic smem: A 64x272 = 17408, W 128x272 = 34816
#define G3_OFF_A 0
#define G3_OFF_W 17408
#define G3_DYN   52224

// scratch (device globals; no allocations allowed)
__device__ float  g_Asrc[NPT*CC];
__device__ float  g_Adst[NPT*CC];
__device__ float  g_V[NPT*CC];
__device__ int    g_idx[NPT*KMAX];
__device__ int    g_cnt[NPT];
__device__ __half g_WT3[3*CC*CC];   // [mat][n][k] fp16, row-major 128

// ---------------------------------------------------------------------------
__device__ __forceinline__ unsigned smem_u32(const void* p) {
    unsigned a;
    asm("{ .reg .u64 t; cvta.to.shared.u64 t, %1; cvt.u32.u64 %0, t; }" : "=r"(a) : "l"(p));
    return a;
}

__device__ __forceinline__ void ldsm4(unsigned* r, unsigned addr) {
    asm volatile("ldmatrix.sync.aligned.m8n8.x4.shared.b16 {%0,%1,%2,%3}, [%4];"
        : "=r"(r[0]), "=r"(r[1]), "=r"(r[2]), "=r"(r[3]) : "r"(addr));
}

__device__ __forceinline__ void mma16816(float* d, const unsigned* a, unsigned b0, unsigned b1) {
    asm volatile("mma.sync.aligned.m16n8k16.row.col.f32.f16.f16.f32 "
        "{%0,%1,%2,%3}, {%4,%5,%6,%7}, {%8,%9}, {%0,%1,%2,%3};"
        : "+f"(d[0]), "+f"(d[1]), "+f"(d[2]), "+f"(d[3])
        : "r"(a[0]), "r"(a[1]), "r"(a[2]), "r"(a[3]), "r"(b0), "r"(b1));
}

// XOR-swizzled eS addressing (float index), conflict-free for both the
// fragment-store pattern (r bits 0-2 + cl bits 1-2 vary) and the aggregate
// read pattern (cl bits 0-4 vary).
__device__ __forceinline__ int eaddr(int r, int cl) {
    int rot = (r & 1) | ((r & 6) << 2);
    return (r << 6) + (cl & 32) + ((cl ^ rot) & 31);
}

// ---------------------------------------------------------------------------
// convert w_{lin,src,dst} -> g_WT3[mat][n][k] fp16
// ---------------------------------------------------------------------------
__global__ __launch_bounds__(256)
void convert_w_kernel(const float* __restrict__ wl,
                      const float* __restrict__ ws,
                      const float* __restrict__ wd)
{
    int idx = blockIdx.x * 256 + threadIdx.x;
    if (idx >= 3 * CC * CC) return;
    int mat = idx >> 14;
    int n   = (idx >> 7) & 127;
    int k   = idx & 127;
    const float* W = (mat == 0) ? wl : (mat == 1) ? ws : wd;
    g_WT3[idx] = __float2half_rn(W[k * CC + n]);
}

// ---------------------------------------------------------------------------
// Kernel A: three GEMMs via HMMA. Grid 128 CTAs x 128 thr (4 warps),
// each CTA: 64 x-rows, loops over the 3 weight matrices.
// ---------------------------------------------------------------------------
__global__ __launch_bounds__(128)
void gemm3_tc_kernel(const float* __restrict__ x)
{
    extern __shared__ __align__(16) char smem[];
    const unsigned sb = smem_u32(smem);
    const int t    = threadIdx.x;
    const int w    = t >> 5;
    const int lane = t & 31;
    const int row0 = blockIdx.x * 64;

    // A: x rows -> fp16 smem (stride 136 halves)
    for (int q = t; q < 64 * CC; q += 128) {
        int row = q >> 7, c = q & 127;
        *(__half*)(smem + G3_OFF_A + row * ASTR_B + c * 2) =
            __float2half_rn(x[(size_t)(row0 + row) * CC + c]);
    }

    const unsigned aBase = sb + G3_OFF_A +
        (unsigned)((w * 16 + (lane & 15)) * ASTR_B + ((lane >> 4) << 4));
    const unsigned bBase = sb + G3_OFF_W +
        (unsigned)((((lane >> 4) << 3) + (lane & 7)) * ASTR_B + (((lane >> 3) & 1) << 4));

    for (int mat = 0; mat < 3; mat++) {
        // copy WT3[mat] (row-major 128 halves) into smem stride-136 layout
        const uint4* src = (const uint4*)(g_WT3 + mat * CC * CC);
        for (int q = t; q < CC * 16; q += 128) {
            int n = q >> 4, seg = q & 15;
            *(uint4*)(smem + G3_OFF_W + n * ASTR_B + seg * 16) = src[n * 16 + seg];
        }
        __syncthreads();

        float acc[16][4];
        #pragma unroll
        for (int nt = 0; nt < 16; nt++) {
            acc[nt][0] = 0.f; acc[nt][1] = 0.f; acc[nt][2] = 0.f; acc[nt][3] = 0.f;
        }
        #pragma unroll
        for (int kk = 0; kk < 8; kk++) {
            unsigned afr[4];
            ldsm4(afr, aBase + kk * 32);
            #pragma unroll
            for (int pp = 0; pp < 8; pp++) {
                unsigned bfr[4];
                ldsm4(bfr, bBase + (unsigned)(pp * 16 * ASTR_B) + kk * 32);
                mma16816(acc[2 * pp],     afr, bfr[0], bfr[1]);
                mma16816(acc[2 * pp + 1], afr, bfr[2], bfr[3]);
            }
        }

        float* O = (mat == 0) ? g_V : (mat == 1) ? g_Asrc : g_Adst;
        int r0 = w * 16 + (lane >> 2);
        int c0 = 2 * (lane & 3);
        #pragma unroll
        for (int nt = 0; nt < 16; nt++) {
            int col = nt * 8 + c0;
            *(float2*)&O[(size_t)(row0 + r0) * CC + col]     = make_float2(acc[nt][0], acc[nt][1]);
            *(float2*)&O[(size_t)(row0 + r0 + 8) * CC + col] = make_float2(acc[nt][2], acc[nt][3]);
        }
        __syncthreads();   // before overwriting W smem
    }
}

// ---------------------------------------------------------------------------
// Kernel C: HMMA fused attention. Persistent, 2 targets per iteration.
// ---------------------------------------------------------------------------
__global__ __launch_bounds__(256, 2)
void main_tc_kernel(const float* __restrict__ pos,
                    const float* __restrict__ nrm,
                    const float* __restrict__ w_pos,
                    const float* __restrict__ b_pos,
                    const float* __restrict__ pos_gamma,
                    const float* __restrict__ pos_beta,
                    const float* __restrict__ pos_mean,
                    const float* __restrict__ pos_var,
                    const float* __restrict__ w_attn,
                    const float* __restrict__ b_attn,
                    const float* __restrict__ attn_gamma,
                    const float* __restrict__ attn_beta,
                    const float* __restrict__ attn_mean,
                    const float* __restrict__ attn_var,
                    float* __restrict__ out)
{
    extern __shared__ __align__(16) char smem[];
    const unsigned sb = smem_u32(smem);

    const int t    = threadIdx.x;
    const int w    = t >> 5;
    const int lane = t & 31;

    float* eS   = (float*)(smem + OFF_A);     // overlays A after MMA
    float* relS = (float*)(smem + OFF_REL);
    int*   idxS = (int*)  (smem + OFF_IDX);
    float* redS = (float*)(smem + OFF_RED);
    float* wpfS = (float*)(smem + OFF_WPF);
    float* bpS  = (float*)(smem + OFF_BP);
    float* saS  = (float*)(smem + OFF_SA);
    float* baS  = (float*)(smem + OFF_BA);
    int*   mS   = (int*)  (smem + OFF_M);

    // per-channel folded-BN constants
    if (t < 128) {
        int c = t;
        float sp = rsqrtf(pos_var[c] + 1e-5f) * pos_gamma[c];
        bpS[c] = (b_pos[c] - pos_mean[c]) * sp + pos_beta[c];
        #pragma unroll
        for (int r = 0; r < 6; r++) wpfS[r * 128 + c] = w_pos[r * 128 + c] * sp;
        float sa = rsqrtf(attn_var[c] + 1e-5f) * attn_gamma[c];
        saS[c] = sa;
        baS[c] = (b_attn[c] - attn_mean[c]) * sa + attn_beta[c];
    }

    // BT[n][k] = w_attn[k][n] fp16 (once per CTA)
    for (int q = t; q < 128 * 128; q += 256) {
        int n = q & 127, k = q >> 7;
        *(__half*)(smem + OFF_B + n * ASTR_B + k * 2) = __float2half_rn(w_attn[k * 128 + n]);
    }
    __syncthreads();

    for (int p = blockIdx.x; p < NPAIR; p += GRID_MAIN) {
        const int i0 = 2 * p;
        __syncthreads();   // prev-iter epilogue done (eS/rel/idx reuse)

        // --- neighbor metadata: rel6, idx, m for both targets ---
        if (t < 2) mS[t] = g_cnt[i0 + t];
        if (t < 128) {
            int tgt = t >> 6, k = t & 63;
            int i = i0 + tgt;
            int m = g_cnt[i];
            int cb = (i >> 10) << 10;
            int jj = (k < m) ? g_idx[i * KMAX + k] : 0;
            idxS[t] = jj;
            int gj = cb + jj;
            float r0 = 0, r1 = 0, r2 = 0, r3 = 0, r4 = 0, r5 = 0;
            if (k < m) {
                r0 = pos[i * 3 + 0] - pos[gj * 3 + 0];
                r1 = pos[i * 3 + 1] - pos[gj * 3 + 1];
                r2 = pos[i * 3 + 2] - pos[gj * 3 + 2];
                r3 = nrm[i * 3 + 0] - nrm[gj * 3 + 0];
                r4 = nrm[i * 3 + 1] - nrm[gj * 3 + 1];
                r5 = nrm[i * 3 + 2] - nrm[gj * 3 + 2];
            }
            relS[t * 8 + 0] = r0; relS[t * 8 + 1] = r1; relS[t * 8 + 2] = r2;
            relS[t * 8 + 3] = r3; relS[t * 8 + 4] = r4; relS[t * 8 + 5] = r5;
        }
        __syncthreads();

        // --- build A: pre[row = tgt*64 + k][col = cin] fp16, real rows only ---
        {
            int tgt = t >> 7;
            int c   = t & 127;
            int i   = i0 + tgt;
            int cb  = (i >> 10) << 10;
            int mt  = mS[tgt];
            int tb  = tgt * 64;
            float ad = g_Adst[i * CC + c];
            float bp = bpS[c];
            float wp0 = wpfS[0 * 128 + c], wp1 = wpfS[1 * 128 + c], wp2 = wpfS[2 * 128 + c];
            float wp3 = wpfS[3 * 128 + c], wp4 = wpfS[4 * 128 + c], wp5 = wpfS[5 * 128 + c];

            float buf[8];
            #pragma unroll
            for (int kp = 0; kp < 8; kp++)
                buf[kp] = (kp < mt) ? g_Asrc[(size_t)(cb + idxS[tb + kp]) * CC + c] : 0.f;

            int k = 0;
            #define A_BODY(KK, AS) do {                                           \
                const float* rl = &relS[(tb + (KK)) * 8];                         \
                float d = bp;                                                     \
                d = fmaf(rl[0], wp0, d); d = fmaf(rl[1], wp1, d);                 \
                d = fmaf(rl[2], wp2, d); d = fmaf(rl[3], wp3, d);                 \
                d = fmaf(rl[4], wp4, d); d = fmaf(rl[5], wp5, d);                 \
                d = fmaxf(d, 0.f);                                                \
                *(__half*)(smem + OFF_A + (tb + (KK)) * ASTR_B + c * 2) =         \
                    __float2half_rn(ad - (AS) + d);                               \
            } while (0)

            for (; k + 8 <= mt; k += 8) {
                #pragma unroll
                for (int j = 0; j < 8; j++) {
                    float as = buf[j];
                    buf[j] = (k + 8 + j < mt)
                           ? g_Asrc[(size_t)(cb + idxS[tb + k + 8 + j]) * CC + c] : 0.f;
                    A_BODY(k + j, as);
                }
            }
            #pragma unroll
            for (int j = 0; j < 8; j++)
                if (k + j < mt) A_BODY(k + j, buf[j]);
            #undef A_BODY
        }
        __syncthreads();

        // --- HMMA: warp w computes rows [w*16, w*16+16) x all 128 couts ---
        // Skip warps whose rows are entirely past their target's count.
        const int  wmt     = mS[w >> 2];
        const bool wactive = ((w & 3) * 16) < wmt;

        float acc[16][4];
        #pragma unroll
        for (int nt = 0; nt < 16; nt++) {
            acc[nt][0] = 0.f; acc[nt][1] = 0.f; acc[nt][2] = 0.f; acc[nt][3] = 0.f;
        }
        if (wactive) {
            const unsigned aBase = sb + OFF_A +
                (unsigned)((w * 16 + (lane & 15)) * ASTR_B + ((lane >> 4) << 4));
            const unsigned bBase = sb + OFF_B +
                (unsigned)((((lane >> 4) << 3) + (lane & 7)) * ASTR_B + (((lane >> 3) & 1) << 4));

            #pragma unroll
            for (int kk = 0; kk < 8; kk++) {
                unsigned afr[4];
                ldsm4(afr, aBase + kk * 32);
                #pragma unroll
                for (int pp = 0; pp < 8; pp++) {
                    unsigned bfr[4];
                    ldsm4(bfr, bBase + (unsigned)(pp * 16 * ASTR_B) + kk * 32);
                    mma16816(acc[2 * pp],     afr, bfr[0], bfr[1]);
                    mma16816(acc[2 * pp + 1], afr, bfr[2], bfr[3]);
                }
            }
        }
        __syncthreads();   // all warps done reading A -> eS may overlay it

        // aggregate-role constants (same thread plays both roles)
        const int cl    = t & 63;
        const int g     = t >> 6;
        const int tgt   = g >> 1;
        const int cb    = ((i0 + tgt) >> 10) << 10;
        const int mt    = mS[tgt];
        const int klb   = (g & 1) << 5;
        const int rowb  = g << 5;
        const int ibase = tgt * 64;
        const int jend0 = min(32, mt - klb);   // may be <= 0

        // --- epilogue: 2 halves of 64 couts each ---
        for (int cc = 0; cc < 2; cc++) {
            const int cp = cc * 64 + cl;

            // (1) V prefetch first: loads in flight during eS stores + barrier
            float vbuf[8];
            if (jend0 > 0) {
                #pragma unroll
                for (int kp = 0; kp < 8; kp++)
                    vbuf[kp] = (kp < jend0)
                             ? g_V[(size_t)(cb + idxS[ibase + klb + kp]) * CC + cp] : 0.f;
            }

            // (2) store this half's alphas (pre-affine) to eS
            if (wactive) {
                int r0 = w * 16 + (lane >> 2);
                int c0 = 2 * (lane & 3);
                #pragma unroll
                for (int ntl = 0; ntl < 8; ntl++) {
                    int nt = cc * 8 + ntl;
                    int cle = ntl * 8 + c0;
                    eS[eaddr(r0,     cle)]     = acc[nt][0];
                    eS[eaddr(r0,     cle + 1)] = acc[nt][1];
                    eS[eaddr(r0 + 8, cle)]     = acc[nt][2];
                    eS[eaddr(r0 + 8, cle + 1)] = acc[nt][3];
                }
            }
            __syncthreads();

            // (3) aggregate
            float fs = 0.f, fa = 0.f;
            if (jend0 > 0) {
                float sa = saS[cp], ba = baS[cp], bp = bpS[cp];
                float wp[6];
                #pragma unroll
                for (int r6 = 0; r6 < 6; r6++) wp[r6] = wpfS[r6 * 128 + cp];

                #define E_BODY(JJ, VV) do {                                       \
                    const float* rl = &relS[(ibase + klb + (JJ)) * 8];            \
                    float d = bp;                                                 \
                    d = fmaf(rl[0], wp[0], d); d = fmaf(rl[1], wp[1], d);         \
                    d = fmaf(rl[2], wp[2], d); d = fmaf(rl[3], wp[3], d);         \
                    d = fmaf(rl[4], wp[4], d); d = fmaf(rl[5], wp[5], d);         \
                    d = fmaxf(d, 0.f);                                            \
                    float alpha = fmaxf(fmaf(eS[eaddr(rowb + (JJ), cl)], sa, ba), 0.f); \
                    float e = __expf(alpha);                                      \
                    fs += e;                                                      \
                    fa = fmaf(e, (VV) + d, fa);                                   \
                } while (0)

                int j = 0;
                for (; j + 8 <= jend0; j += 8) {
                    #pragma unroll
                    for (int jj = 0; jj < 8; jj++) {
                        float v = vbuf[jj];
                        vbuf[jj] = (j + 8 + jj < jend0)
                                 ? g_V[(size_t)(cb + idxS[ibase + klb + j + 8 + jj]) * CC + cp] : 0.f;
                        E_BODY(j + jj, v);
                    }
                }
                #pragma unroll
                for (int jj = 0; jj < 8; jj++)
                    if (j + jj < jend0) E_BODY(j + jj, vbuf[jj]);
                #undef E_BODY
            }
            redS[(g * 64 + cl) * 2 + 0] = fs;
            redS[(g * 64 + cl) * 2 + 1] = fa;
            __syncthreads();

            if (t < 128) {
                int tg2 = t >> 6, cl2 = t & 63;
                int cp2 = cc * 64 + cl2;
                int g0 = tg2 * 2;
                float den = redS[(g0 * 64 + cl2) * 2 + 0] + redS[((g0 + 1) * 64 + cl2) * 2 + 0];
                float num = redS[(g0 * 64 + cl2) * 2 + 1] + redS[((g0 + 1) * 64 + cl2) * 2 + 1];
                out[(size_t)(i0 + tg2) * CC + cp2] = num / den;
            }
        }
    }
}

// ---------------------------------------------------------------------------
// Kernel B: radius + nearest-K selection (smem-staged cloud)
// ---------------------------------------------------------------------------
__global__ __launch_bounds__(128)
void neigh_kernel(const float* __restrict__ pos)
{
    const int t     = threadIdx.x;
    const int lane  = t & 31;
    const int wid   = t >> 5;
    const int i0    = blockIdx.x * 4;
    const int cbase = (i0 >> 10) << 10;

    __shared__ float pos_s[PP * 3];
    __shared__ int   red[4];

    for (int idx = t; idx < PP * 3; idx += 128)
        pos_s[idx] = pos[cbase * 3 + idx];
    __syncthreads();

    const unsigned R2b = __float_as_uint(0.04f);

    for (int tt = 0; tt < 4; tt++) {
        const int i  = i0 + tt;
        const int li = i - cbase;
        const float px = pos_s[li * 3 + 0];
        const float py = pos_s[li * 3 + 1];
        const float pz = pos_s[li * 3 + 2];

        unsigned bits[8];
        #pragma unroll
        for (int q = 0; q < 8; q++) {
            int j = q * 128 + t;
            float dx = px - pos_s[j * 3 + 0];
            float dy = py - pos_s[j * 3 + 1];
            float dz = pz - pos_s[j * 3 + 2];
            float d2 = dx * dx + dy * dy + dz * dz;
            bits[q] = __float_as_uint(d2);   // >=0 floats: bit order == value order
        }

        int local = 0;
        #pragma unroll
        for (int q = 0; q < 8; q++) local += (bits[q] <= R2b);
        #pragma unroll
        for (int o = 16; o > 0; o >>= 1) local += __shfl_down_sync(0xffffffffu, local, o);
        if (lane == 0) red[wid] = local;
        __syncthreads();
        int total = red[0] + red[1] + red[2] + red[3];
        __syncthreads();

        unsigned th = R2b;
        if (total > KMAX) {
            unsigned lo = 0, hi = R2b;
            while (lo < hi) {
                unsigned mid = lo + ((hi - lo) >> 1);
                int cnt = 0;
                #pragma unroll
                for (int q = 0; q < 8; q++) cnt += (bits[q] <= mid);
                #pragma unroll
                for (int o = 16; o > 0; o >>= 1) cnt += __shfl_down_sync(0xffffffffu, cnt, o);
                if (lane == 0) red[wid] = cnt;
                __syncthreads();
                int tot = red[0] + red[1] + red[2] + red[3];
                __syncthreads();
                if (tot >= KMAX) hi = mid; else lo = mid + 1;
            }
            th = lo;
        }

        int wbase = 0;
        for (int q = 0; q < 8; q++) {
            bool sel = (bits[q] <= th);
            unsigned ball = __ballot_sync(0xffffffffu, sel);
            if (lane == 0) red[wid] = __popc(ball);
            __syncthreads();
            int woff = 0;
            #pragma unroll
            for (int ww = 0; ww < 4; ww++) if (ww < wid) woff += red[ww];
            int tot = red[0] + red[1] + red[2] + red[3];
            int rank = wbase + woff + __popc(ball & ((1u << lane) - 1u));
            if (sel && rank < KMAX) g_idx[i * KMAX + rank] = q * 128 + t;
            wbase += tot;
            __syncthreads();
        }
        if (t == 0) g_cnt[i] = (wbase < KMAX) ? wbase : KMAX;
        __syncthreads();
    }
}

// ---------------------------------------------------------------------------
extern "C" void kernel_launch(void* const* d_in, const int* in_sizes, int n_in,
                              void* d_out, int out_size)
{
    const float* x      = (const float*)d_in[0];
    const float* pos    = (const float*)d_in[1];
    const float* nrm    = (const float*)d_in[2];
    // d_in[3] = batch (structured, unused)
    const float* w_lin  = (const float*)d_in[4];
    const float* w_src  = (const float*)d_in[5];
    const float* w_dst  = (const float*)d_in[6];
    const float* w_pos  = (const float*)d_in[7];
    const float* b_pos  = (const float*)d_in[8];
    const float* pos_g  = (const float*)d_in[9];
    const float* pos_b  = (const float*)d_in[10];
    const float* pos_m  = (const float*)d_in[11];
    const float* pos_v  = (const float*)d_in[12];
    const float* w_attn = (const float*)d_in[13];
    const float* b_attn = (const float*)d_in[14];
    const float* attn_g = (const float*)d_in[15];
    const float* attn_b = (const float*)d_in[16];
    const float* attn_m = (const float*)d_in[17];
    const float* attn_v = (const float*)d_in[18];
    float* out = (float*)d_out;

    cudaFuncSetAttribute(main_tc_kernel,
                         cudaFuncAttributeMaxDynamicSharedMemorySize, DYN_SIZE);
    cudaFuncSetAttribute(gemm3_tc_kernel,
                         cudaFuncAttributeMaxDynamicSharedMemorySize, G3_DYN);

    convert_w_kernel<<<192, 256>>>(w_lin, w_src, w_dst);
    gemm3_tc_kernel<<<128, 128, G3_DYN>>>(x);
    neigh_kernel<<<NPT / 4, 128>>>(pos);
    main_tc_kernel<<<GRID_MAIN, 256, DYN_SIZE>>>(
        pos, nrm, w_pos, b_pos, pos_g, pos_b, pos_m, pos_v,
        w_attn, b_attn, attn_g, attn_b, attn_m, attn_v, out);
}

// round 10
// speedup vs baseline: 2.7369x; 1.2876x over previous
#include <cuda_runtime.h>
#include <cuda_fp16.h>
#include <math.h>

#define NPT   8192
#define CC    128
#define PP    1024
#define KMAX  64
#define NPAIR (NPT/2)
#define GRID_MAIN 296

// ---- main kernel dynamic smem layout (byte offsets) ----
// A (fp16 MMA operand, swizzled 128x256B) is overlaid by eS (fp16 alphas) after MMA.
#define OFF_A     0
#define OFF_B     32768
#define OFF_DELTA 65536
#define OFF_REL   98304
#define OFF_IDX   102400
#define OFF_WPF   102912
#define OFF_BP    105984
#define OFF_SA    106496
#define OFF_BA    107008
#define OFF_M     107520
#define DYN_SIZE  107648

// gemm3 dynamic smem (padded layout, unchanged from working version)
#define ASTR_B   272
#define G3_OFF_A 0
#define G3_OFF_W 17408
#define G3_DYN   52224

// scratch (device globals; no allocations allowed)
__device__ float  g_Asrc[NPT*CC];
__device__ float  g_Adst[NPT*CC];
__device__ float  g_V[NPT*CC];
__device__ int    g_idx[NPT*KMAX];
__device__ int    g_cnt[NPT];
__device__ __half g_WT3[3*CC*CC];   // [mat][n][k] fp16

// ---------------------------------------------------------------------------
__device__ __forceinline__ unsigned smem_u32(const void* p) {
    unsigned a;
    asm("{ .reg .u64 t; cvta.to.shared.u64 t, %1; cvt.u32.u64 %0, t; }" : "=r"(a) : "l"(p));
    return a;
}

__device__ __forceinline__ void ldsm4(unsigned* r, unsigned addr) {
    asm volatile("ldmatrix.sync.aligned.m8n8.x4.shared.b16 {%0,%1,%2,%3}, [%4];"
        : "=r"(r[0]), "=r"(r[1]), "=r"(r[2]), "=r"(r[3]) : "r"(addr));
}

__device__ __forceinline__ void mma16816(float* d, const unsigned* a, unsigned b0, unsigned b1) {
    asm volatile("mma.sync.aligned.m16n8k16.row.col.f32.f16.f16.f32 "
        "{%0,%1,%2,%3}, {%4,%5,%6,%7}, {%8,%9}, {%0,%1,%2,%3};"
        : "+f"(d[0]), "+f"(d[1]), "+f"(d[2]), "+f"(d[3])
        : "r"(a[0]), "r"(a[1]), "r"(a[2]), "r"(a[3]), "r"(b0), "r"(b1));
}

// fp16 tile addressing: 128 ch per 256B row, 16B-unit XOR swizzle (conflict-free
// for ldmatrix reads, per-channel stores, fragment stores, and row-wise reads).
__device__ __forceinline__ int haddr(int row, int ch) {
    return (row << 8) + ((((ch >> 3) ^ (row & 7)) & 15) << 4) + ((ch & 7) << 1);
}

// ---------------------------------------------------------------------------
__global__ __launch_bounds__(256)
void convert_w_kernel(const float* __restrict__ wl,
                      const float* __restrict__ ws,
                      const float* __restrict__ wd)
{
    int idx = blockIdx.x * 256 + threadIdx.x;
    if (idx >= 3 * CC * CC) return;
    int mat = idx >> 14;
    int n   = (idx >> 7) & 127;
    int k   = idx & 127;
    const float* W = (mat == 0) ? wl : (mat == 1) ? ws : wd;
    g_WT3[idx] = __float2half_rn(W[k * CC + n]);
}

// ---------------------------------------------------------------------------
// Kernel A: three GEMMs via HMMA (unchanged working version).
// ---------------------------------------------------------------------------
__global__ __launch_bounds__(128)
void gemm3_tc_kernel(const float* __restrict__ x)
{
    extern __shared__ __align__(16) char smem[];
    const unsigned sb = smem_u32(smem);
    const int t    = threadIdx.x;
    const int w    = t >> 5;
    const int lane = t & 31;
    const int row0 = blockIdx.x * 64;

    for (int q = t; q < 64 * CC; q += 128) {
        int row = q >> 7, c = q & 127;
        *(__half*)(smem + G3_OFF_A + row * ASTR_B + c * 2) =
            __float2half_rn(x[(size_t)(row0 + row) * CC + c]);
    }

    const unsigned aBase = sb + G3_OFF_A +
        (unsigned)((w * 16 + (lane & 15)) * ASTR_B + ((lane >> 4) << 4));
    const unsigned bBase = sb + G3_OFF_W +
        (unsigned)((((lane >> 4) << 3) + (lane & 7)) * ASTR_B + (((lane >> 3) & 1) << 4));

    for (int mat = 0; mat < 3; mat++) {
        const uint4* src = (const uint4*)(g_WT3 + mat * CC * CC);
        for (int q = t; q < CC * 16; q += 128) {
            int n = q >> 4, seg = q & 15;
            *(uint4*)(smem + G3_OFF_W + n * ASTR_B + seg * 16) = src[n * 16 + seg];
        }
        __syncthreads();

        float acc[16][4];
        #pragma unroll
        for (int nt = 0; nt < 16; nt++) {
            acc[nt][0] = 0.f; acc[nt][1] = 0.f; acc[nt][2] = 0.f; acc[nt][3] = 0.f;
        }
        #pragma unroll
        for (int kk = 0; kk < 8; kk++) {
            unsigned afr[4];
            ldsm4(afr, aBase + kk * 32);
            #pragma unroll
            for (int pp = 0; pp < 8; pp++) {
                unsigned bfr[4];
                ldsm4(bfr, bBase + (unsigned)(pp * 16 * ASTR_B) + kk * 32);
                mma16816(acc[2 * pp],     afr, bfr[0], bfr[1]);
                mma16816(acc[2 * pp + 1], afr, bfr[2], bfr[3]);
            }
        }

        float* O = (mat == 0) ? g_V : (mat == 1) ? g_Asrc : g_Adst;
        int r0 = w * 16 + (lane >> 2);
        int c0 = 2 * (lane & 3);
        #pragma unroll
        for (int nt = 0; nt < 16; nt++) {
            int col = nt * 8 + c0;
            *(float2*)&O[(size_t)(row0 + r0) * CC + col]     = make_float2(acc[nt][0], acc[nt][1]);
            *(float2*)&O[(size_t)(row0 + r0 + 8) * CC + col] = make_float2(acc[nt][2], acc[nt][3]);
        }
        __syncthreads();
    }
}

// ---------------------------------------------------------------------------
// Kernel C: HMMA fused attention. Persistent, 2 targets/iter, 5 barriers/iter.
// ---------------------------------------------------------------------------
__global__ __launch_bounds__(256, 2)
void main_tc_kernel(const float* __restrict__ pos,
                    const float* __restrict__ nrm,
                    const float* __restrict__ w_pos,
                    const float* __restrict__ b_pos,
                    const float* __restrict__ pos_gamma,
                    const float* __restrict__ pos_beta,
                    const float* __restrict__ pos_mean,
                    const float* __restrict__ pos_var,
                    const float* __restrict__ w_attn,
                    const float* __restrict__ b_attn,
                    const float* __restrict__ attn_gamma,
                    const float* __restrict__ attn_beta,
                    const float* __restrict__ attn_mean,
                    const float* __restrict__ attn_var,
                    float* __restrict__ out)
{
    extern __shared__ __align__(16) char smem[];
    const unsigned sb = smem_u32(smem);

    const int t    = threadIdx.x;
    const int w    = t >> 5;
    const int lane = t & 31;

    float* relS = (float*)(smem + OFF_REL);
    int*   idxS = (int*)  (smem + OFF_IDX);
    float* wpfS = (float*)(smem + OFF_WPF);
    float* bpS  = (float*)(smem + OFF_BP);
    float* saS  = (float*)(smem + OFF_SA);
    float* baS  = (float*)(smem + OFF_BA);
    int*   mS   = (int*)  (smem + OFF_M);

    // per-channel folded-BN constants
    if (t < 128) {
        int c = t;
        float sp = rsqrtf(pos_var[c] + 1e-5f) * pos_gamma[c];
        bpS[c] = (b_pos[c] - pos_mean[c]) * sp + pos_beta[c];
        #pragma unroll
        for (int r = 0; r < 6; r++) wpfS[r * 128 + c] = w_pos[r * 128 + c] * sp;
        float sa = rsqrtf(attn_var[c] + 1e-5f) * attn_gamma[c];
        saS[c] = sa;
        baS[c] = (b_attn[c] - attn_mean[c]) * sa + attn_beta[c];
    }

    // B[n][k] = w_attn[k][n] fp16 into swizzled tile (once per CTA)
    for (int q = t; q < 128 * 128; q += 256) {
        int n = q & 127, k = q >> 7;
        *(__half*)(smem + OFF_B + haddr(n, k)) = __float2half_rn(w_attn[k * 128 + n]);
    }
    __syncthreads();

    for (int p = blockIdx.x; p < NPAIR; p += GRID_MAIN) {
        const int i0 = 2 * p;
        __syncthreads();   // prev-iter epilogue reads (eS, deltaS, idxS) done

        // --- metadata: all 256 threads; part0 = pos+idx, part1 = nrm ---
        if (t < 2) mS[t] = g_cnt[i0 + t];
        {
            int k2   = t & 127;
            int part = t >> 7;
            int tgt  = k2 >> 6, kk = k2 & 63;
            int i    = i0 + tgt;
            int cb   = (i >> 10) << 10;
            int jj   = g_idx[i * KMAX + kk];   // always in-bounds (see theory)
            int gj   = cb + jj;
            if (part == 0) {
                idxS[k2] = jj;
                relS[k2 * 8 + 0] = pos[i * 3 + 0] - pos[gj * 3 + 0];
                relS[k2 * 8 + 1] = pos[i * 3 + 1] - pos[gj * 3 + 1];
                relS[k2 * 8 + 2] = pos[i * 3 + 2] - pos[gj * 3 + 2];
            } else {
                relS[k2 * 8 + 3] = nrm[i * 3 + 0] - nrm[gj * 3 + 0];
                relS[k2 * 8 + 4] = nrm[i * 3 + 1] - nrm[gj * 3 + 1];
                relS[k2 * 8 + 5] = nrm[i * 3 + 2] - nrm[gj * 3 + 2];
            }
        }
        __syncthreads();

        // --- build A (fp16, swizzled) + deltaS (fp16), real rows only ---
        {
            int tgt = t >> 7;
            int c   = t & 127;
            int i   = i0 + tgt;
            int cb  = (i >> 10) << 10;
            int mt  = mS[tgt];
            int tb  = tgt * 64;
            float ad = g_Adst[i * CC + c];
            float bp = bpS[c];
            float wp0 = wpfS[0 * 128 + c], wp1 = wpfS[1 * 128 + c], wp2 = wpfS[2 * 128 + c];
            float wp3 = wpfS[3 * 128 + c], wp4 = wpfS[4 * 128 + c], wp5 = wpfS[5 * 128 + c];

            float buf[8];
            #pragma unroll
            for (int kp = 0; kp < 8; kp++)
                buf[kp] = (kp < mt) ? g_Asrc[(size_t)(cb + idxS[tb + kp]) * CC + c] : 0.f;

            int k = 0;
            #define A_BODY(KK, AS) do {                                           \
                const float* rl = &relS[(tb + (KK)) * 8];                         \
                float d = bp;                                                     \
                d = fmaf(rl[0], wp0, d); d = fmaf(rl[1], wp1, d);                 \
                d = fmaf(rl[2], wp2, d); d = fmaf(rl[3], wp3, d);                 \
                d = fmaf(rl[4], wp4, d); d = fmaf(rl[5], wp5, d);                 \
                d = fmaxf(d, 0.f);                                                \
                int ha = haddr(tb + (KK), c);                                     \
                *(__half*)(smem + OFF_DELTA + ha) = __float2half_rn(d);           \
                *(__half*)(smem + OFF_A + ha) = __float2half_rn(ad - (AS) + d);   \
            } while (0)

            for (; k + 8 <= mt; k += 8) {
                #pragma unroll
                for (int j = 0; j < 8; j++) {
                    float as = buf[j];
                    buf[j] = (k + 8 + j < mt)
                           ? g_Asrc[(size_t)(cb + idxS[tb + k + 8 + j]) * CC + c] : 0.f;
                    A_BODY(k + j, as);
                }
            }
            #pragma unroll
            for (int j = 0; j < 8; j++)
                if (k + j < mt) A_BODY(k + j, buf[j]);
            #undef A_BODY
        }
        __syncthreads();

        // --- HMMA: warp w -> rows [w*16, w*16+16) x 128 couts; skip empty warps ---
        const int  wmt     = mS[w >> 2];
        const bool wactive = ((w & 3) * 16) < wmt;

        float acc[16][4];
        #pragma unroll
        for (int nt = 0; nt < 16; nt++) {
            acc[nt][0] = 0.f; acc[nt][1] = 0.f; acc[nt][2] = 0.f; acc[nt][3] = 0.f;
        }
        if (wactive) {
            const int r    = w * 16 + (lane & 15);
            const int u0a  = lane >> 4;
            const int xr   = lane & 7;              // == r & 7 == n-row & 7
            const unsigned aRow = sb + OFF_A + (unsigned)(r << 8);
            const int nrow0 = ((lane >> 4) << 3) + (lane & 7);
            const int u0b  = (lane >> 3) & 1;
            const unsigned bRow = sb + OFF_B + (unsigned)(nrow0 << 8);

            #pragma unroll
            for (int kk = 0; kk < 8; kk++) {
                unsigned afr[4];
                ldsm4(afr, aRow + (unsigned)((((kk * 2 + u0a) ^ xr) & 15) << 4));
                #pragma unroll
                for (int pp = 0; pp < 8; pp++) {
                    unsigned bfr[4];
                    ldsm4(bfr, bRow + (unsigned)(pp << 12)
                               + (unsigned)((((kk * 2 + u0b) ^ xr) & 15) << 4));
                    mma16816(acc[2 * pp],     afr, bfr[0], bfr[1]);
                    mma16816(acc[2 * pp + 1], afr, bfr[2], bfr[3]);
                }
            }
        }
        __syncthreads();   // MMA reads of A done -> eS may overlay A

        // --- store all alphas (pre-affine) as fp16 into eS (overlay A) ---
        if (wactive) {
            int r0 = w * 16 + (lane >> 2);
            int c0 = 2 * (lane & 3);
            #pragma unroll
            for (int nt = 0; nt < 16; nt++) {
                int c = nt * 8 + c0;
                *(__half2*)(smem + OFF_A + haddr(r0, c)) =
                    __floats2half2_rn(acc[nt][0], acc[nt][1]);
                *(__half2*)(smem + OFF_A + haddr(r0 + 8, c)) =
                    __floats2half2_rn(acc[nt][2], acc[nt][3]);
            }
        }
        __syncthreads();

        // --- aggregate: thread = (tgt = t>>7, cp = t&127), full k-loop, no reduction ---
        {
            const int tgt   = t >> 7;
            const int cp    = t & 127;
            const int i     = i0 + tgt;
            const int cb    = (i >> 10) << 10;
            const int mt    = mS[tgt];
            const int ibase = tgt * 64;
            const float sa  = saS[cp];
            const float ba  = baS[cp];

            float fs = 0.f, fa = 0.f;
            float vbuf[8];
            #pragma unroll
            for (int kp = 0; kp < 8; kp++)
                vbuf[kp] = (kp < mt) ? g_V[(size_t)(cb + idxS[ibase + kp]) * CC + cp] : 0.f;

            #define E_BODY(KK, VV) do {                                           \
                int ha = haddr(ibase + (KK), cp);                                 \
                float ar = __half2float(*(const __half*)(smem + OFF_A + ha));     \
                float dd = __half2float(*(const __half*)(smem + OFF_DELTA + ha)); \
                float alpha = fmaxf(fmaf(ar, sa, ba), 0.f);                       \
                float e = __expf(alpha);                                          \
                fs += e;                                                          \
                fa = fmaf(e, (VV) + dd, fa);                                      \
            } while (0)

            int k = 0;
            for (; k + 8 <= mt; k += 8) {
                #pragma unroll
                for (int j = 0; j < 8; j++) {
                    float v = vbuf[j];
                    vbuf[j] = (k + 8 + j < mt)
                            ? g_V[(size_t)(cb + idxS[ibase + k + 8 + j]) * CC + cp] : 0.f;
                    E_BODY(k + j, v);
                }
            }
            #pragma unroll
            for (int j = 0; j < 8; j++)
                if (k + j < mt) E_BODY(k + j, vbuf[j]);
            #undef E_BODY

            out[(size_t)i * CC + cp] = fa / fs;
        }
    }
}

// ---------------------------------------------------------------------------
// Kernel B: radius + nearest-K selection (smem-staged cloud)
// ---------------------------------------------------------------------------
__global__ __launch_bounds__(128)
void neigh_kernel(const float* __restrict__ pos)
{
    const int t     = threadIdx.x;
    const int lane  = t & 31;
    const int wid   = t >> 5;
    const int i0    = blockIdx.x * 4;
    const int cbase = (i0 >> 10) << 10;

    __shared__ float pos_s[PP * 3];
    __shared__ int   red[4];

    for (int idx = t; idx < PP * 3; idx += 128)
        pos_s[idx] = pos[cbase * 3 + idx];
    __syncthreads();

    const unsigned R2b = __float_as_uint(0.04f);

    for (int tt = 0; tt < 4; tt++) {
        const int i  = i0 + tt;
        const int li = i - cbase;
        const float px = pos_s[li * 3 + 0];
        const float py = pos_s[li * 3 + 1];
        const float pz = pos_s[li * 3 + 2];

        unsigned bits[8];
        #pragma unroll
        for (int q = 0; q < 8; q++) {
            int j = q * 128 + t;
            float dx = px - pos_s[j * 3 + 0];
            float dy = py - pos_s[j * 3 + 1];
            float dz = pz - pos_s[j * 3 + 2];
            float d2 = dx * dx + dy * dy + dz * dz;
            bits[q] = __float_as_uint(d2);   // >=0 floats: bit order == value order
        }

        int local = 0;
        #pragma unroll
        for (int q = 0; q < 8; q++) local += (bits[q] <= R2b);
        #pragma unroll
        for (int o = 16; o > 0; o >>= 1) local += __shfl_down_sync(0xffffffffu, local, o);
        if (lane == 0) red[wid] = local;
        __syncthreads();
        int total = red[0] + red[1] + red[2] + red[3];
        __syncthreads();

        unsigned th = R2b;
        if (total > KMAX) {
            unsigned lo = 0, hi = R2b;
            while (lo < hi) {
                unsigned mid = lo + ((hi - lo) >> 1);
                int cnt = 0;
                #pragma unroll
                for (int q = 0; q < 8; q++) cnt += (bits[q] <= mid);
                #pragma unroll
                for (int o = 16; o > 0; o >>= 1) cnt += __shfl_down_sync(0xffffffffu, cnt, o);
                if (lane == 0) red[wid] = cnt;
                __syncthreads();
                int tot = red[0] + red[1] + red[2] + red[3];
                __syncthreads();
                if (tot >= KMAX) hi = mid; else lo = mid + 1;
            }
            th = lo;
        }

        int wbase = 0;
        for (int q = 0; q < 8; q++) {
            bool sel = (bits[q] <= th);
            unsigned ball = __ballot_sync(0xffffffffu, sel);
            if (lane == 0) red[wid] = __popc(ball);
            __syncthreads();
            int woff = 0;
            #pragma unroll
            for (int ww = 0; ww < 4; ww++) if (ww < wid) woff += red[ww];
            int tot = red[0] + red[1] + red[2] + red[3];
            int rank = wbase + woff + __popc(ball & ((1u << lane) - 1u));
            if (sel && rank < KMAX) g_idx[i * KMAX + rank] = q * 128 + t;
            wbase += tot;
            __syncthreads();
        }
        if (t == 0) g_cnt[i] = (wbase < KMAX) ? wbase : KMAX;
        __syncthreads();
    }
}

// ---------------------------------------------------------------------------
extern "C" void kernel_launch(void* const* d_in, const int* in_sizes, int n_in,
                              void* d_out, int out_size)
{
    const float* x      = (const float*)d_in[0];
    const float* pos    = (const float*)d_in[1];
    const float* nrm    = (const float*)d_in[2];
    // d_in[3] = batch (structured, unused)
    const float* w_lin  = (const float*)d_in[4];
    const float* w_src  = (const float*)d_in[5];
    const float* w_dst  = (const float*)d_in[6];
    const float* w_pos  = (const float*)d_in[7];
    const float* b_pos  = (const float*)d_in[8];
    const float* pos_g  = (const float*)d_in[9];
    const float* pos_b  = (const float*)d_in[10];
    const float* pos_m  = (const float*)d_in[11];
    const float* pos_v  = (const float*)d_in[12];
    const float* w_attn = (const float*)d_in[13];
    const float* b_attn = (const float*)d_in[14];
    const float* attn_g = (const float*)d_in[15];
    const float* attn_b = (const float*)d_in[16];
    const float* attn_m = (const float*)d_in[17];
    const float* attn_v = (const float*)d_in[18];
    float* out = (float*)d_out;

    cudaFuncSetAttribute(main_tc_kernel,
                         cudaFuncAttributeMaxDynamicSharedMemorySize, DYN_SIZE);
    cudaFuncSetAttribute(gemm3_tc_kernel,
                         cudaFuncAttributeMaxDynamicSharedMemorySize, G3_DYN);

    convert_w_kernel<<<192, 256>>>(w_lin, w_src, w_dst);
    gemm3_tc_kernel<<<128, 128, G3_DYN>>>(x);
    neigh_kernel<<<NPT / 4, 128>>>(pos);
    main_tc_kernel<<<GRID_MAIN, 256, DYN_SIZE>>>(
        pos, nrm, w_pos, b_pos, pos_g, pos_b, pos_m, pos_v,
        w_attn, b_attn, attn_g, attn_b, attn_m, attn_v, out);
}

// round 11
// speedup vs baseline: 3.1046x; 1.1343x over previous
#include <cuda_runtime.h>
#include <cuda_fp16.h>
#include <math.h>

#define NPT   8192
#define CC    128
#define PP    1024
#define KMAX  64
#define NPAIR (NPT/2)
#define GRID_MAIN 296

// ---- main kernel dynamic smem layout (byte offsets) ----
// A (fp16 MMA operand, swizzled 128x256B) overlaid by eS (fp16 alphas) after MMA.
// redS (4KB) overlays relS (dead after A-build).
#define OFF_A     0
#define OFF_B     32768
#define OFF_DELTA 65536
#define OFF_REL   98304
#define OFF_RED   98304
#define OFF_IDX   102400
#define OFF_WPF   102912
#define OFF_BP    105984
#define OFF_SA    106496
#define OFF_BA    107008
#define OFF_M     107520
#define DYN_SIZE  107648

// gemm3 dynamic smem (padded layout)
#define ASTR_B   272
#define G3_OFF_A 0
#define G3_OFF_W 17408
#define G3_DYN   52224

// scratch (device globals; zero-initialized at load; no allocations allowed)
__device__ float  g_Asrc[NPT*CC];
__device__ float  g_Adst[NPT*CC];
__device__ float  g_V[NPT*CC];
__device__ int    g_idx[NPT*KMAX];
__device__ int    g_cnt[NPT];
__device__ __half g_WT3[3*CC*CC];   // [mat][n][k] fp16

// ---------------------------------------------------------------------------
__device__ __forceinline__ unsigned smem_u32(const void* p) {
    unsigned a;
    asm("{ .reg .u64 t; cvta.to.shared.u64 t, %1; cvt.u32.u64 %0, t; }" : "=r"(a) : "l"(p));
    return a;
}

__device__ __forceinline__ void ldsm4(unsigned* r, unsigned addr) {
    asm volatile("ldmatrix.sync.aligned.m8n8.x4.shared.b16 {%0,%1,%2,%3}, [%4];"
        : "=r"(r[0]), "=r"(r[1]), "=r"(r[2]), "=r"(r[3]) : "r"(addr));
}

__device__ __forceinline__ void mma16816(float* d, const unsigned* a, unsigned b0, unsigned b1) {
    asm volatile("mma.sync.aligned.m16n8k16.row.col.f32.f16.f16.f32 "
        "{%0,%1,%2,%3}, {%4,%5,%6,%7}, {%8,%9}, {%0,%1,%2,%3};"
        : "+f"(d[0]), "+f"(d[1]), "+f"(d[2]), "+f"(d[3])
        : "r"(a[0]), "r"(a[1]), "r"(a[2]), "r"(a[3]), "r"(b0), "r"(b1));
}

__device__ __forceinline__ float ex2f(float x) {
    float y;
    asm("ex2.approx.ftz.f32 %0, %1;" : "=f"(y) : "f"(x));
    return y;
}

// fp16 tile addressing: 128 ch per 256B row, 16B-unit XOR swizzle.
__device__ __forceinline__ int haddr(int row, int ch) {
    return (row << 8) + ((((ch >> 3) ^ (row & 7)) & 15) << 4) + ((ch & 7) << 1);
}

// ---------------------------------------------------------------------------
__global__ __launch_bounds__(256)
void convert_w_kernel(const float* __restrict__ wl,
                      const float* __restrict__ ws,
                      const float* __restrict__ wd)
{
    int idx = blockIdx.x * 256 + threadIdx.x;
    if (idx >= 3 * CC * CC) return;
    int mat = idx >> 14;
    int n   = (idx >> 7) & 127;
    int k   = idx & 127;
    const float* W = (mat == 0) ? wl : (mat == 1) ? ws : wd;
    g_WT3[idx] = __float2half_rn(W[k * CC + n]);
}

// ---------------------------------------------------------------------------
// Kernel A: three GEMMs via HMMA.
// ---------------------------------------------------------------------------
__global__ __launch_bounds__(128)
void gemm3_tc_kernel(const float* __restrict__ x)
{
    extern __shared__ __align__(16) char smem[];
    const unsigned sb = smem_u32(smem);
    const int t    = threadIdx.x;
    const int w    = t >> 5;
    const int lane = t & 31;
    const int row0 = blockIdx.x * 64;

    for (int q = t; q < 64 * CC; q += 128) {
        int row = q >> 7, c = q & 127;
        *(__half*)(smem + G3_OFF_A + row * ASTR_B + c * 2) =
            __float2half_rn(x[(size_t)(row0 + row) * CC + c]);
    }

    const unsigned aBase = sb + G3_OFF_A +
        (unsigned)((w * 16 + (lane & 15)) * ASTR_B + ((lane >> 4) << 4));
    const unsigned bBase = sb + G3_OFF_W +
        (unsigned)((((lane >> 4) << 3) + (lane & 7)) * ASTR_B + (((lane >> 3) & 1) << 4));

    for (int mat = 0; mat < 3; mat++) {
        const uint4* src = (const uint4*)(g_WT3 + mat * CC * CC);
        for (int q = t; q < CC * 16; q += 128) {
            int n = q >> 4, seg = q & 15;
            *(uint4*)(smem + G3_OFF_W + n * ASTR_B + seg * 16) = src[n * 16 + seg];
        }
        __syncthreads();

        float acc[16][4];
        #pragma unroll
        for (int nt = 0; nt < 16; nt++) {
            acc[nt][0] = 0.f; acc[nt][1] = 0.f; acc[nt][2] = 0.f; acc[nt][3] = 0.f;
        }
        #pragma unroll
        for (int kk = 0; kk < 8; kk++) {
            unsigned afr[4];
            ldsm4(afr, aBase + kk * 32);
            #pragma unroll
            for (int pp = 0; pp < 8; pp++) {
                unsigned bfr[4];
                ldsm4(bfr, bBase + (unsigned)(pp * 16 * ASTR_B) + kk * 32);
                mma16816(acc[2 * pp],     afr, bfr[0], bfr[1]);
                mma16816(acc[2 * pp + 1], afr, bfr[2], bfr[3]);
            }
        }

        float* O = (mat == 0) ? g_V : (mat == 1) ? g_Asrc : g_Adst;
        int r0 = w * 16 + (lane >> 2);
        int c0 = 2 * (lane & 3);
        #pragma unroll
        for (int nt = 0; nt < 16; nt++) {
            int col = nt * 8 + c0;
            *(float2*)&O[(size_t)(row0 + r0) * CC + col]     = make_float2(acc[nt][0], acc[nt][1]);
            *(float2*)&O[(size_t)(row0 + r0 + 8) * CC + col] = make_float2(acc[nt][2], acc[nt][3]);
        }
        __syncthreads();
    }
}

// ---------------------------------------------------------------------------
// Kernel C: HMMA fused attention. Persistent, 2 targets/iter, 5 barriers/iter.
// ---------------------------------------------------------------------------
__global__ __launch_bounds__(256, 2)
void main_tc_kernel(const float* __restrict__ pos,
                    const float* __restrict__ nrm,
                    const float* __restrict__ w_pos,
                    const float* __restrict__ b_pos,
                    const float* __restrict__ pos_gamma,
                    const float* __restrict__ pos_beta,
                    const float* __restrict__ pos_mean,
                    const float* __restrict__ pos_var,
                    const float* __restrict__ w_attn,
                    const float* __restrict__ b_attn,
                    const float* __restrict__ attn_gamma,
                    const float* __restrict__ attn_beta,
                    const float* __restrict__ attn_mean,
                    const float* __restrict__ attn_var,
                    float* __restrict__ out)
{
    extern __shared__ __align__(16) char smem[];
    const unsigned sb = smem_u32(smem);

    const int t    = threadIdx.x;
    const int w    = t >> 5;
    const int lane = t & 31;

    float* relS = (float*)(smem + OFF_REL);
    float* redS = (float*)(smem + OFF_RED);   // overlays relS (dead after A-build)
    int*   idxS = (int*)  (smem + OFF_IDX);   // premultiplied: gj * 128
    float* wpfS = (float*)(smem + OFF_WPF);
    float* bpS  = (float*)(smem + OFF_BP);
    float* saS  = (float*)(smem + OFF_SA);    // pre-scaled by log2(e)
    float* baS  = (float*)(smem + OFF_BA);    // pre-scaled by log2(e)
    int*   mS   = (int*)  (smem + OFF_M);

    // per-channel folded-BN constants
    if (t < 128) {
        int c = t;
        float sp = rsqrtf(pos_var[c] + 1e-5f) * pos_gamma[c];
        bpS[c] = (b_pos[c] - pos_mean[c]) * sp + pos_beta[c];
        #pragma unroll
        for (int r = 0; r < 6; r++) wpfS[r * 128 + c] = w_pos[r * 128 + c] * sp;
        const float L2E = 1.4426950408889634f;
        float sa = rsqrtf(attn_var[c] + 1e-5f) * attn_gamma[c];
        saS[c] = sa * L2E;
        baS[c] = ((b_attn[c] - attn_mean[c]) * sa + attn_beta[c]) * L2E;
    }

    // B[n][k] = w_attn[k][n] fp16 into swizzled tile (once per CTA)
    for (int q = t; q < 128 * 128; q += 256) {
        int n = q & 127, k = q >> 7;
        *(__half*)(smem + OFF_B + haddr(n, k)) = __float2half_rn(w_attn[k * 128 + n]);
    }
    __syncthreads();

    for (int p = blockIdx.x; p < NPAIR; p += GRID_MAIN) {
        const int i0 = 2 * p;
        __syncthreads();   // prev-iter epilogue reads (eS, deltaS, idxS, redS) done

        // --- metadata: all 256 threads; part0 = pos+idx, part1 = nrm ---
        if (t < 2) mS[t] = g_cnt[i0 + t];
        {
            int k2   = t & 127;
            int part = t >> 7;
            int tgt  = k2 >> 6, kk = k2 & 63;
            int i    = i0 + tgt;
            int cb   = (i >> 10) << 10;
            int jj   = g_idx[i * KMAX + kk];   // zero-init / stale but always in-bounds
            int gj   = cb + jj;
            if (part == 0) {
                idxS[k2] = gj * CC;
                relS[k2 * 8 + 0] = pos[i * 3 + 0] - pos[gj * 3 + 0];
                relS[k2 * 8 + 1] = pos[i * 3 + 1] - pos[gj * 3 + 1];
                relS[k2 * 8 + 2] = pos[i * 3 + 2] - pos[gj * 3 + 2];
            } else {
                relS[k2 * 8 + 3] = nrm[i * 3 + 0] - nrm[gj * 3 + 0];
                relS[k2 * 8 + 4] = nrm[i * 3 + 1] - nrm[gj * 3 + 1];
                relS[k2 * 8 + 5] = nrm[i * 3 + 2] - nrm[gj * 3 + 2];
            }
        }
        __syncthreads();

        // --- build A (fp16, swizzled) + deltaS (fp16), real rows only ---
        {
            int tgt = t >> 7;
            int c   = t & 127;
            int i   = i0 + tgt;
            int mt  = mS[tgt];
            int tb  = tgt * 64;
            float ad = g_Adst[i * CC + c];
            float bp = bpS[c];
            float wp0 = wpfS[0 * 128 + c], wp1 = wpfS[1 * 128 + c], wp2 = wpfS[2 * 128 + c];
            float wp3 = wpfS[3 * 128 + c], wp4 = wpfS[4 * 128 + c], wp5 = wpfS[5 * 128 + c];

            float buf[8];
            #pragma unroll
            for (int kp = 0; kp < 8; kp++)
                buf[kp] = (kp < mt) ? g_Asrc[idxS[tb + kp] + c] : 0.f;

            int k = 0;
            #define A_BODY(KK, AS) do {                                           \
                const float4 ra = *(const float4*)&relS[(tb + (KK)) * 8];         \
                const float4 rb = *(const float4*)&relS[(tb + (KK)) * 8 + 4];     \
                float d = bp;                                                     \
                d = fmaf(ra.x, wp0, d); d = fmaf(ra.y, wp1, d);                   \
                d = fmaf(ra.z, wp2, d); d = fmaf(ra.w, wp3, d);                   \
                d = fmaf(rb.x, wp4, d); d = fmaf(rb.y, wp5, d);                   \
                d = fmaxf(d, 0.f);                                                \
                int ha = haddr(tb + (KK), c);                                     \
                *(__half*)(smem + OFF_DELTA + ha) = __float2half_rn(d);           \
                *(__half*)(smem + OFF_A + ha) = __float2half_rn(ad - (AS) + d);   \
            } while (0)

            for (; k + 8 <= mt; k += 8) {
                #pragma unroll
                for (int j = 0; j < 8; j++) {
                    float as = buf[j];
                    buf[j] = (k + 8 + j < mt) ? g_Asrc[idxS[tb + k + 8 + j] + c] : 0.f;
                    A_BODY(k + j, as);
                }
            }
            #pragma unroll
            for (int j = 0; j < 8; j++)
                if (k + j < mt) A_BODY(k + j, buf[j]);
            #undef A_BODY
        }
        __syncthreads();

        // --- HMMA: warp w -> rows [w*16, w*16+16) x 128 couts; skip empty warps.
        // Each warp reads ONLY its own A rows and then stores alphas to the SAME
        // rows (eS overlays A) -> no cross-warp hazard, no barrier in between.
        const int  wmt     = mS[w >> 2];
        const bool wactive = ((w & 3) * 16) < wmt;

        if (wactive) {
            float acc[16][4];
            #pragma unroll
            for (int nt = 0; nt < 16; nt++) {
                acc[nt][0] = 0.f; acc[nt][1] = 0.f; acc[nt][2] = 0.f; acc[nt][3] = 0.f;
            }
            const int r    = w * 16 + (lane & 15);
            const int u0a  = lane >> 4;
            const int xr   = lane & 7;
            const unsigned aRow = sb + OFF_A + (unsigned)(r << 8);
            const int nrow0 = ((lane >> 4) << 3) + (lane & 7);
            const int u0b  = (lane >> 3) & 1;
            const unsigned bRow = sb + OFF_B + (unsigned)(nrow0 << 8);

            #pragma unroll
            for (int kk = 0; kk < 8; kk++) {
                unsigned afr[4];
                ldsm4(afr, aRow + (unsigned)((((kk * 2 + u0a) ^ xr) & 15) << 4));
                #pragma unroll
                for (int pp = 0; pp < 8; pp++) {
                    unsigned bfr[4];
                    ldsm4(bfr, bRow + (unsigned)(pp << 12)
                               + (unsigned)((((kk * 2 + u0b) ^ xr) & 15) << 4));
                    mma16816(acc[2 * pp],     afr, bfr[0], bfr[1]);
                    mma16816(acc[2 * pp + 1], afr, bfr[2], bfr[3]);
                }
            }

            // store alphas (pre-affine) fp16 into eS (overlay of this warp's A rows)
            int r0 = w * 16 + (lane >> 2);
            int c0 = 2 * (lane & 3);
            #pragma unroll
            for (int nt = 0; nt < 16; nt++) {
                int c = nt * 8 + c0;
                *(__half2*)(smem + OFF_A + haddr(r0, c)) =
                    __floats2half2_rn(acc[nt][0], acc[nt][1]);
                *(__half2*)(smem + OFF_A + haddr(r0 + 8, c)) =
                    __floats2half2_rn(acc[nt][2], acc[nt][3]);
            }
        }
        __syncthreads();

        // --- epilogue: thread = (tgt, cp-pair, k-half); half2 smem reads,
        //     float2 coalesced V gathers, 4 fp32 partials, then reduce ---
        {
            const int tgt   = t >> 7;
            const int half  = (t >> 6) & 1;
            const int cpp   = t & 63;
            const int cp    = cpp * 2;
            const int mt    = mS[tgt];
            const int ibase = tgt * 64;
            const int khalf = (mt + 1) >> 1;
            const int kb    = half ? khalf : 0;
            const int ke    = half ? mt : khalf;
            const float2 sa2 = *(const float2*)&saS[cp];
            const float2 ba2 = *(const float2*)&baS[cp];

            float fs0 = 0.f, fs1 = 0.f, fa0 = 0.f, fa1 = 0.f;
            float2 vbuf[4];
            #pragma unroll
            for (int kp = 0; kp < 4; kp++)
                vbuf[kp] = (kb + kp < ke) ? *(const float2*)&g_V[idxS[ibase + kb + kp] + cp]
                                          : make_float2(0.f, 0.f);

            #define E2_BODY(KK, VV) do {                                          \
                int ha = haddr(ibase + (KK), cp);                                 \
                float2 ar = __half22float2(*(const __half2*)(smem + OFF_A + ha)); \
                float2 dd = __half22float2(*(const __half2*)(smem + OFF_DELTA + ha)); \
                float a0 = fmaxf(fmaf(ar.x, sa2.x, ba2.x), 0.f);                  \
                float a1 = fmaxf(fmaf(ar.y, sa2.y, ba2.y), 0.f);                  \
                float e0 = ex2f(a0);                                              \
                float e1 = ex2f(a1);                                              \
                fs0 += e0; fs1 += e1;                                             \
                fa0 = fmaf(e0, (VV).x + dd.x, fa0);                               \
                fa1 = fmaf(e1, (VV).y + dd.y, fa1);                               \
            } while (0)

            int k = kb;
            for (; k + 4 <= ke; k += 4) {
                #pragma unroll
                for (int j = 0; j < 4; j++) {
                    float2 v = vbuf[j];
                    vbuf[j] = (k + 4 + j < ke)
                            ? *(const float2*)&g_V[idxS[ibase + k + 4 + j] + cp]
                            : make_float2(0.f, 0.f);
                    E2_BODY(k + j, v);
                }
            }
            #pragma unroll
            for (int j = 0; j < 4; j++)
                if (k + j < ke) E2_BODY(k + j, vbuf[j]);
            #undef E2_BODY

            *(float4*)&redS[(((half << 1) | tgt) * 64 + cpp) * 4] =
                make_float4(fs0, fs1, fa0, fa1);
        }
        __syncthreads();

        // --- final: merge the two k-halves, normalize, write out ---
        {
            int tg2 = t >> 7, cp2 = t & 127;
            int cq  = cp2 >> 1, s = cp2 & 1;
            const float* r0 = &redS[(tg2 * 64 + cq) * 4];
            const float* r1 = &redS[((2 + tg2) * 64 + cq) * 4];
            float fs = r0[s] + r1[s];
            float fa = r0[2 + s] + r1[2 + s];
            out[(size_t)(i0 + tg2) * CC + cp2] = fa / fs;
        }
    }
}

// ---------------------------------------------------------------------------
// Kernel B: radius + nearest-K selection (smem-staged cloud)
// ---------------------------------------------------------------------------
__global__ __launch_bounds__(128)
void neigh_kernel(const float* __restrict__ pos)
{
    const int t     = threadIdx.x;
    const int lane  = t & 31;
    const int wid   = t >> 5;
    const int i0    = blockIdx.x * 4;
    const int cbase = (i0 >> 10) << 10;

    __shared__ float pos_s[PP * 3];
    __shared__ int   red[4];

    for (int idx = t; idx < PP * 3; idx += 128)
        pos_s[idx] = pos[cbase * 3 + idx];
    __syncthreads();

    const unsigned R2b = __float_as_uint(0.04f);

    for (int tt = 0; tt < 4; tt++) {
        const int i  = i0 + tt;
        const int li = i - cbase;
        const float px = pos_s[li * 3 + 0];
        const float py = pos_s[li * 3 + 1];
        const float pz = pos_s[li * 3 + 2];

        unsigned bits[8];
        #pragma unroll
        for (int q = 0; q < 8; q++) {
            int j = q * 128 + t;
            float dx = px - pos_s[j * 3 + 0];
            float dy = py - pos_s[j * 3 + 1];
            float dz = pz - pos_s[j * 3 + 2];
            float d2 = dx * dx + dy * dy + dz * dz;
            bits[q] = __float_as_uint(d2);
        }

        int local = 0;
        #pragma unroll
        for (int q = 0; q < 8; q++) local += (bits[q] <= R2b);
        #pragma unroll
        for (int o = 16; o > 0; o >>= 1) local += __shfl_down_sync(0xffffffffu, local, o);
        if (lane == 0) red[wid] = local;
        __syncthreads();
        int total = red[0] + red[1] + red[2] + red[3];
        __syncthreads();

        unsigned th = R2b;
        if (total > KMAX) {
            unsigned lo = 0, hi = R2b;
            while (lo < hi) {
                unsigned mid = lo + ((hi - lo) >> 1);
                int cnt = 0;
                #pragma unroll
                for (int q = 0; q < 8; q++) cnt += (bits[q] <= mid);
                #pragma unroll
                for (int o = 16; o > 0; o >>= 1) cnt += __shfl_down_sync(0xffffffffu, cnt, o);
                if (lane == 0) red[wid] = cnt;
                __syncthreads();
                int tot = red[0] + red[1] + red[2] + red[3];
                __syncthreads();
                if (tot >= KMAX) hi = mid; else lo = mid + 1;
            }
            th = lo;
        }

        int wbase = 0;
        for (int q = 0; q < 8; q++) {
            bool sel = (bits[q] <= th);
            unsigned ball = __ballot_sync(0xffffffffu, sel);
            if (lane == 0) red[wid] = __popc(ball);
            __syncthreads();
            int woff = 0;
            #pragma unroll
            for (int ww = 0; ww < 4; ww++) if (ww < wid) woff += red[ww];
            int tot = red[0] + red[1] + red[2] + red[3];
            int rank = wbase + woff + __popc(ball & ((1u << lane) - 1u));
            if (sel && rank < KMAX) g_idx[i * KMAX + rank] = q * 128 + t;
            wbase += tot;
            __syncthreads();
        }
        if (t == 0) g_cnt[i] = (wbase < KMAX) ? wbase : KMAX;
        __syncthreads();
    }
}

// ---------------------------------------------------------------------------
extern "C" void kernel_launch(void* const* d_in, const int* in_sizes, int n_in,
                              void* d_out, int out_size)
{
    const float* x      = (const float*)d_in[0];
    const float* pos    = (const float*)d_in[1];
    const float* nrm    = (const float*)d_in[2];
    // d_in[3] = batch (structured, unused)
    const float* w_lin  = (const float*)d_in[4];
    const float* w_src  = (const float*)d_in[5];
    const float* w_dst  = (const float*)d_in[6];
    const float* w_pos  = (const float*)d_in[7];
    const float* b_pos  = (const float*)d_in[8];
    const float* pos_g  = (const float*)d_in[9];
    const float* pos_b  = (const float*)d_in[10];
    const float* pos_m  = (const float*)d_in[11];
    const float* pos_v  = (const float*)d_in[12];
    const float* w_attn = (const float*)d_in[13];
    const float* b_attn = (const float*)d_in[14];
    const float* attn_g = (const float*)d_in[15];
    const float* attn_b = (const float*)d_in[16];
    const float* attn_m = (const float*)d_in[17];
    const float* attn_v = (const float*)d_in[18];
    float* out = (float*)d_out;

    cudaFuncSetAttribute(main_tc_kernel,
                         cudaFuncAttributeMaxDynamicSharedMemorySize, DYN_SIZE);
    cudaFuncSetAttribute(gemm3_tc_kernel,
                         cudaFuncAttributeMaxDynamicSharedMemorySize, G3_DYN);

    convert_w_kernel<<<192, 256>>>(w_lin, w_src, w_dst);
    gemm3_tc_kernel<<<128, 128, G3_DYN>>>(x);
    neigh_kernel<<<NPT / 4, 128>>>(pos);
    main_tc_kernel<<<GRID_MAIN, 256, DYN_SIZE>>>(
        pos, nrm, w_pos, b_pos, pos_g, pos_b, pos_m, pos_v,
        w_attn, b_attn, attn_g, attn_b, attn_m, attn_v, out);
}

// round 12
// speedup vs baseline: 3.2174x; 1.0363x over previous
#include <cuda_runtime.h>
#include <cuda_fp16.h>
#include <math.h>

#define NPT   8192
#define CC    128
#define PP    1024
#define KMAX  64
#define NPAIR (NPT/2)
#define GRID_MAIN 296

// ---- main kernel dynamic smem layout (byte offsets) ----
// A (fp16 MMA operand, swizzled 128x256B) overlaid by eS (fp16 alphas) after MMA.
// VD holds (V + delta) fp16. redS (4KB) overlays relS (dead after A-build).
#define OFF_A     0
#define OFF_B     32768
#define OFF_VD    65536
#define OFF_REL   98304
#define OFF_RED   98304
#define OFF_IDX   102400
#define OFF_WPF   102912
#define OFF_BP    105984
#define OFF_SA    106496
#define OFF_BA    107008
#define OFF_M     107520
#define DYN_SIZE  107648

// gemm3 dynamic smem (padded layout)
#define ASTR_B   272
#define G3_OFF_A 0
#define G3_OFF_W 17408
#define G3_DYN   52224

// scratch (device globals; zero-initialized at load; no allocations allowed)
__device__ float2 g_AV[NPT*CC];     // .x = x@w_src (Asrc), .y = x@w_lin (V)
__device__ float  g_Adst[NPT*CC];
__device__ int    g_idx[NPT*KMAX];
__device__ int    g_cnt[NPT];
__device__ __half g_WT3[3*CC*CC];   // [mat][n][k] fp16

// ---------------------------------------------------------------------------
__device__ __forceinline__ unsigned smem_u32(const void* p) {
    unsigned a;
    asm("{ .reg .u64 t; cvta.to.shared.u64 t, %1; cvt.u32.u64 %0, t; }" : "=r"(a) : "l"(p));
    return a;
}

__device__ __forceinline__ void ldsm4(unsigned* r, unsigned addr) {
    asm volatile("ldmatrix.sync.aligned.m8n8.x4.shared.b16 {%0,%1,%2,%3}, [%4];"
        : "=r"(r[0]), "=r"(r[1]), "=r"(r[2]), "=r"(r[3]) : "r"(addr));
}

__device__ __forceinline__ void mma16816(float* d, const unsigned* a, unsigned b0, unsigned b1) {
    asm volatile("mma.sync.aligned.m16n8k16.row.col.f32.f16.f16.f32 "
        "{%0,%1,%2,%3}, {%4,%5,%6,%7}, {%8,%9}, {%0,%1,%2,%3};"
        : "+f"(d[0]), "+f"(d[1]), "+f"(d[2]), "+f"(d[3])
        : "r"(a[0]), "r"(a[1]), "r"(a[2]), "r"(a[3]), "r"(b0), "r"(b1));
}

__device__ __forceinline__ float ex2f(float x) {
    float y;
    asm("ex2.approx.ftz.f32 %0, %1;" : "=f"(y) : "f"(x));
    return y;
}

// fp16 tile addressing: 128 ch per 256B row, 16B-unit XOR swizzle.
__device__ __forceinline__ int haddr(int row, int ch) {
    return (row << 8) + ((((ch >> 3) ^ (row & 7)) & 15) << 4) + ((ch & 7) << 1);
}

// ---------------------------------------------------------------------------
__global__ __launch_bounds__(256)
void convert_w_kernel(const float* __restrict__ wl,
                      const float* __restrict__ ws,
                      const float* __restrict__ wd)
{
    int idx = blockIdx.x * 256 + threadIdx.x;
    if (idx >= 3 * CC * CC) return;
    int mat = idx >> 14;
    int n   = (idx >> 7) & 127;
    int k   = idx & 127;
    const float* W = (mat == 0) ? wl : (mat == 1) ? ws : wd;
    g_WT3[idx] = __float2half_rn(W[k * CC + n]);
}

// ---------------------------------------------------------------------------
// Kernel A: three GEMMs via HMMA. mat0 (w_lin) -> g_AV.y, mat1 (w_src) -> g_AV.x,
// mat2 (w_dst) -> g_Adst.
// ---------------------------------------------------------------------------
__global__ __launch_bounds__(128)
void gemm3_tc_kernel(const float* __restrict__ x)
{
    extern __shared__ __align__(16) char smem[];
    const unsigned sb = smem_u32(smem);
    const int t    = threadIdx.x;
    const int w    = t >> 5;
    const int lane = t & 31;
    const int row0 = blockIdx.x * 64;

    for (int q = t; q < 64 * CC; q += 128) {
        int row = q >> 7, c = q & 127;
        *(__half*)(smem + G3_OFF_A + row * ASTR_B + c * 2) =
            __float2half_rn(x[(size_t)(row0 + row) * CC + c]);
    }

    const unsigned aBase = sb + G3_OFF_A +
        (unsigned)((w * 16 + (lane & 15)) * ASTR_B + ((lane >> 4) << 4));
    const unsigned bBase = sb + G3_OFF_W +
        (unsigned)((((lane >> 4) << 3) + (lane & 7)) * ASTR_B + (((lane >> 3) & 1) << 4));

    for (int mat = 0; mat < 3; mat++) {
        const uint4* src = (const uint4*)(g_WT3 + mat * CC * CC);
        for (int q = t; q < CC * 16; q += 128) {
            int n = q >> 4, seg = q & 15;
            *(uint4*)(smem + G3_OFF_W + n * ASTR_B + seg * 16) = src[n * 16 + seg];
        }
        __syncthreads();

        float acc[16][4];
        #pragma unroll
        for (int nt = 0; nt < 16; nt++) {
            acc[nt][0] = 0.f; acc[nt][1] = 0.f; acc[nt][2] = 0.f; acc[nt][3] = 0.f;
        }
        #pragma unroll
        for (int kk = 0; kk < 8; kk++) {
            unsigned afr[4];
            ldsm4(afr, aBase + kk * 32);
            #pragma unroll
            for (int pp = 0; pp < 8; pp++) {
                unsigned bfr[4];
                ldsm4(bfr, bBase + (unsigned)(pp * 16 * ASTR_B) + kk * 32);
                mma16816(acc[2 * pp],     afr, bfr[0], bfr[1]);
                mma16816(acc[2 * pp + 1], afr, bfr[2], bfr[3]);
            }
        }

        int r0 = w * 16 + (lane >> 2);
        int c0 = 2 * (lane & 3);
        if (mat == 2) {
            #pragma unroll
            for (int nt = 0; nt < 16; nt++) {
                int col = nt * 8 + c0;
                *(float2*)&g_Adst[(size_t)(row0 + r0) * CC + col] =
                    make_float2(acc[nt][0], acc[nt][1]);
                *(float2*)&g_Adst[(size_t)(row0 + r0 + 8) * CC + col] =
                    make_float2(acc[nt][2], acc[nt][3]);
            }
        } else if (mat == 0) {
            #pragma unroll
            for (int nt = 0; nt < 16; nt++) {
                int col = nt * 8 + c0;
                size_t b0i = (size_t)(row0 + r0) * CC + col;
                size_t b1i = (size_t)(row0 + r0 + 8) * CC + col;
                g_AV[b0i].y     = acc[nt][0];
                g_AV[b0i + 1].y = acc[nt][1];
                g_AV[b1i].y     = acc[nt][2];
                g_AV[b1i + 1].y = acc[nt][3];
            }
        } else {
            #pragma unroll
            for (int nt = 0; nt < 16; nt++) {
                int col = nt * 8 + c0;
                size_t b0i = (size_t)(row0 + r0) * CC + col;
                size_t b1i = (size_t)(row0 + r0 + 8) * CC + col;
                g_AV[b0i].x     = acc[nt][0];
                g_AV[b0i + 1].x = acc[nt][1];
                g_AV[b1i].x     = acc[nt][2];
                g_AV[b1i + 1].x = acc[nt][3];
            }
        }
        __syncthreads();
    }
}

// ---------------------------------------------------------------------------
// Kernel C: HMMA fused attention. Persistent, 2 targets/iter.
// Single gather phase (LDG.64 of (Asrc,V)); epilogue is pure smem/ALU.
// ---------------------------------------------------------------------------
__global__ __launch_bounds__(256, 2)
void main_tc_kernel(const float* __restrict__ pos,
                    const float* __restrict__ nrm,
                    const float* __restrict__ w_pos,
                    const float* __restrict__ b_pos,
                    const float* __restrict__ pos_gamma,
                    const float* __restrict__ pos_beta,
                    const float* __restrict__ pos_mean,
                    const float* __restrict__ pos_var,
                    const float* __restrict__ w_attn,
                    const float* __restrict__ b_attn,
                    const float* __restrict__ attn_gamma,
                    const float* __restrict__ attn_beta,
                    const float* __restrict__ attn_mean,
                    const float* __restrict__ attn_var,
                    float* __restrict__ out)
{
    extern __shared__ __align__(16) char smem[];
    const unsigned sb = smem_u32(smem);

    const int t    = threadIdx.x;
    const int w    = t >> 5;
    const int lane = t & 31;

    float* relS = (float*)(smem + OFF_REL);
    float* redS = (float*)(smem + OFF_RED);   // overlays relS (dead after A-build)
    int*   idxS = (int*)  (smem + OFF_IDX);   // premultiplied: gj * 128
    float* wpfS = (float*)(smem + OFF_WPF);
    float* bpS  = (float*)(smem + OFF_BP);
    float* saS  = (float*)(smem + OFF_SA);    // pre-scaled by log2(e)
    float* baS  = (float*)(smem + OFF_BA);    // pre-scaled by log2(e)
    int*   mS   = (int*)  (smem + OFF_M);

    // per-channel folded-BN constants
    if (t < 128) {
        int c = t;
        float sp = rsqrtf(pos_var[c] + 1e-5f) * pos_gamma[c];
        bpS[c] = (b_pos[c] - pos_mean[c]) * sp + pos_beta[c];
        #pragma unroll
        for (int r = 0; r < 6; r++) wpfS[r * 128 + c] = w_pos[r * 128 + c] * sp;
        const float L2E = 1.4426950408889634f;
        float sa = rsqrtf(attn_var[c] + 1e-5f) * attn_gamma[c];
        saS[c] = sa * L2E;
        baS[c] = ((b_attn[c] - attn_mean[c]) * sa + attn_beta[c]) * L2E;
    }

    // B[n][k] = w_attn[k][n] fp16 into swizzled tile (once per CTA)
    for (int q = t; q < 128 * 128; q += 256) {
        int n = q & 127, k = q >> 7;
        *(__half*)(smem + OFF_B + haddr(n, k)) = __float2half_rn(w_attn[k * 128 + n]);
    }
    __syncthreads();

    for (int p = blockIdx.x; p < NPAIR; p += GRID_MAIN) {
        const int i0 = 2 * p;
        __syncthreads();   // prev-iter epilogue reads (eS, vdS, idxS, redS) done

        // --- metadata: all 256 threads; part0 = pos+idx, part1 = nrm ---
        if (t < 2) mS[t] = g_cnt[i0 + t];
        {
            int k2   = t & 127;
            int part = t >> 7;
            int tgt  = k2 >> 6, kk = k2 & 63;
            int i    = i0 + tgt;
            int cb   = (i >> 10) << 10;
            int jj   = g_idx[i * KMAX + kk];   // stale/zero-init but always in-bounds
            int gj   = cb + jj;
            if (part == 0) {
                idxS[k2] = gj * CC;
                relS[k2 * 8 + 0] = pos[i * 3 + 0] - pos[gj * 3 + 0];
                relS[k2 * 8 + 1] = pos[i * 3 + 1] - pos[gj * 3 + 1];
                relS[k2 * 8 + 2] = pos[i * 3 + 2] - pos[gj * 3 + 2];
            } else {
                relS[k2 * 8 + 3] = nrm[i * 3 + 0] - nrm[gj * 3 + 0];
                relS[k2 * 8 + 4] = nrm[i * 3 + 1] - nrm[gj * 3 + 1];
                relS[k2 * 8 + 5] = nrm[i * 3 + 2] - nrm[gj * 3 + 2];
            }
        }
        __syncthreads();

        // --- build A (fp16, swizzled) + vdS = V + delta (fp16); one LDG.64/k ---
        {
            int tgt = t >> 7;
            int c   = t & 127;
            int i   = i0 + tgt;
            int mt  = mS[tgt];
            int tb  = tgt * 64;
            float ad = g_Adst[i * CC + c];
            float bp = bpS[c];
            float wp0 = wpfS[0 * 128 + c], wp1 = wpfS[1 * 128 + c], wp2 = wpfS[2 * 128 + c];
            float wp3 = wpfS[3 * 128 + c], wp4 = wpfS[4 * 128 + c], wp5 = wpfS[5 * 128 + c];

            float2 buf[8];
            #pragma unroll
            for (int kp = 0; kp < 8; kp++)
                buf[kp] = (kp < mt) ? g_AV[idxS[tb + kp] + c] : make_float2(0.f, 0.f);

            int k = 0;
            #define A_BODY(KK, AV) do {                                           \
                const float4 ra = *(const float4*)&relS[(tb + (KK)) * 8];         \
                const float4 rb = *(const float4*)&relS[(tb + (KK)) * 8 + 4];     \
                float d = bp;                                                     \
                d = fmaf(ra.x, wp0, d); d = fmaf(ra.y, wp1, d);                   \
                d = fmaf(ra.z, wp2, d); d = fmaf(ra.w, wp3, d);                   \
                d = fmaf(rb.x, wp4, d); d = fmaf(rb.y, wp5, d);                   \
                d = fmaxf(d, 0.f);                                                \
                int ha = haddr(tb + (KK), c);                                     \
                *(__half*)(smem + OFF_VD + ha) = __float2half_rn((AV).y + d);     \
                *(__half*)(smem + OFF_A + ha) = __float2half_rn(ad - (AV).x + d); \
            } while (0)

            for (; k + 8 <= mt; k += 8) {
                #pragma unroll
                for (int j = 0; j < 8; j++) {
                    float2 av = buf[j];
                    buf[j] = (k + 8 + j < mt) ? g_AV[idxS[tb + k + 8 + j] + c]
                                              : make_float2(0.f, 0.f);
                    A_BODY(k + j, av);
                }
            }
            #pragma unroll
            for (int j = 0; j < 8; j++)
                if (k + j < mt) A_BODY(k + j, buf[j]);
            #undef A_BODY
        }
        __syncthreads();

        // --- HMMA: warp w -> rows [w*16, w*16+16) x 128 couts; skip empty warps.
        // Each warp reads ONLY its own A rows then overlays alphas on the same
        // rows -> no cross-warp hazard, no barrier in between.
        const int  wmt     = mS[w >> 2];
        const bool wactive = ((w & 3) * 16) < wmt;

        if (wactive) {
            float acc[16][4];
            #pragma unroll
            for (int nt = 0; nt < 16; nt++) {
                acc[nt][0] = 0.f; acc[nt][1] = 0.f; acc[nt][2] = 0.f; acc[nt][3] = 0.f;
            }
            const int r    = w * 16 + (lane & 15);
            const int u0a  = lane >> 4;
            const int xr   = lane & 7;
            const unsigned aRow = sb + OFF_A + (unsigned)(r << 8);
            const int nrow0 = ((lane >> 4) << 3) + (lane & 7);
            const int u0b  = (lane >> 3) & 1;
            const unsigned bRow = sb + OFF_B + (unsigned)(nrow0 << 8);

            #pragma unroll
            for (int kk = 0; kk < 8; kk++) {
                unsigned afr[4];
                ldsm4(afr, aRow + (unsigned)((((kk * 2 + u0a) ^ xr) & 15) << 4));
                #pragma unroll
                for (int pp = 0; pp < 8; pp++) {
                    unsigned bfr[4];
                    ldsm4(bfr, bRow + (unsigned)(pp << 12)
                               + (unsigned)((((kk * 2 + u0b) ^ xr) & 15) << 4));
                    mma16816(acc[2 * pp],     afr, bfr[0], bfr[1]);
                    mma16816(acc[2 * pp + 1], afr, bfr[2], bfr[3]);
                }
            }

            // store alphas (pre-affine) fp16 into eS (overlay of this warp's A rows)
            int r0 = w * 16 + (lane >> 2);
            int c0 = 2 * (lane & 3);
            #pragma unroll
            for (int nt = 0; nt < 16; nt++) {
                int c = nt * 8 + c0;
                *(__half2*)(smem + OFF_A + haddr(r0, c)) =
                    __floats2half2_rn(acc[nt][0], acc[nt][1]);
                *(__half2*)(smem + OFF_A + haddr(r0 + 8, c)) =
                    __floats2half2_rn(acc[nt][2], acc[nt][3]);
            }
        }
        __syncthreads();

        // --- epilogue (pure smem): thread = (tgt, cp-pair, k-half) ---
        {
            const int tgt   = t >> 7;
            const int half  = (t >> 6) & 1;
            const int cpp   = t & 63;
            const int cp    = cpp * 2;
            const int mt    = mS[tgt];
            const int ibase = tgt * 64;
            const int khalf = (mt + 1) >> 1;
            const int kb    = half ? khalf : 0;
            const int ke    = half ? mt : khalf;
            const float2 sa2 = *(const float2*)&saS[cp];
            const float2 ba2 = *(const float2*)&baS[cp];

            float fs0 = 0.f, fs1 = 0.f, fa0 = 0.f, fa1 = 0.f;

            #define E2_BODY(KK) do {                                              \
                int ha = haddr(ibase + (KK), cp);                                 \
                float2 ar = __half22float2(*(const __half2*)(smem + OFF_A + ha)); \
                float2 vd = __half22float2(*(const __half2*)(smem + OFF_VD + ha)); \
                float a0 = fmaxf(fmaf(ar.x, sa2.x, ba2.x), 0.f);                  \
                float a1 = fmaxf(fmaf(ar.y, sa2.y, ba2.y), 0.f);                  \
                float e0 = ex2f(a0);                                              \
                float e1 = ex2f(a1);                                              \
                fs0 += e0; fs1 += e1;                                             \
                fa0 = fmaf(e0, vd.x, fa0);                                        \
                fa1 = fmaf(e1, vd.y, fa1);                                        \
            } while (0)

            int k = kb;
            for (; k + 4 <= ke; k += 4) {
                E2_BODY(k); E2_BODY(k + 1); E2_BODY(k + 2); E2_BODY(k + 3);
            }
            for (; k < ke; k++) E2_BODY(k);
            #undef E2_BODY

            *(float4*)&redS[(((half << 1) | tgt) * 64 + cpp) * 4] =
                make_float4(fs0, fs1, fa0, fa1);
        }
        __syncthreads();

        // --- final: merge the two k-halves, normalize, write out ---
        {
            int tg2 = t >> 7, cp2 = t & 127;
            int cq  = cp2 >> 1, s = cp2 & 1;
            const float* r0 = &redS[(tg2 * 64 + cq) * 4];
            const float* r1 = &redS[((2 + tg2) * 64 + cq) * 4];
            float fs = r0[s] + r1[s];
            float fa = r0[2 + s] + r1[2 + s];
            out[(size_t)(i0 + tg2) * CC + cp2] = fa / fs;
        }
    }
}

// ---------------------------------------------------------------------------
// Kernel B: radius + nearest-K selection (smem-staged cloud)
// ---------------------------------------------------------------------------
__global__ __launch_bounds__(128)
void neigh_kernel(const float* __restrict__ pos)
{
    const int t     = threadIdx.x;
    const int lane  = t & 31;
    const int wid   = t >> 5;
    const int i0    = blockIdx.x * 4;
    const int cbase = (i0 >> 10) << 10;

    __shared__ float pos_s[PP * 3];
    __shared__ int   red[4];

    for (int idx = t; idx < PP * 3; idx += 128)
        pos_s[idx] = pos[cbase * 3 + idx];
    __syncthreads();

    const unsigned R2b = __float_as_uint(0.04f);

    for (int tt = 0; tt < 4; tt++) {
        const int i  = i0 + tt;
        const int li = i - cbase;
        const float px = pos_s[li * 3 + 0];
        const float py = pos_s[li * 3 + 1];
        const float pz = pos_s[li * 3 + 2];

        unsigned bits[8];
        #pragma unroll
        for (int q = 0; q < 8; q++) {
            int j = q * 128 + t;
            float dx = px - pos_s[j * 3 + 0];
            float dy = py - pos_s[j * 3 + 1];
            float dz = pz - pos_s[j * 3 + 2];
            float d2 = dx * dx + dy * dy + dz * dz;
            bits[q] = __float_as_uint(d2);
        }

        int local = 0;
        #pragma unroll
        for (int q = 0; q < 8; q++) local += (bits[q] <= R2b);
        #pragma unroll
        for (int o = 16; o > 0; o >>= 1) local += __shfl_down_sync(0xffffffffu, local, o);
        if (lane == 0) red[wid] = local;
        __syncthreads();
        int total = red[0] + red[1] + red[2] + red[3];
        __syncthreads();

        unsigned th = R2b;
        if (total > KMAX) {
            unsigned lo = 0, hi = R2b;
            while (lo < hi) {
                unsigned mid = lo + ((hi - lo) >> 1);
                int cnt = 0;
                #pragma unroll
                for (int q = 0; q < 8; q++) cnt += (bits[q] <= mid);
                #pragma unroll
                for (int o = 16; o > 0; o >>= 1) cnt += __shfl_down_sync(0xffffffffu, cnt, o);
                if (lane == 0) red[wid] = cnt;
                __syncthreads();
                int tot = red[0] + red[1] + red[2] + red[3];
                __syncthreads();
                if (tot >= KMAX) hi = mid; else lo = mid + 1;
            }
            th = lo;
        }

        int wbase = 0;
        for (int q = 0; q < 8; q++) {
            bool sel = (bits[q] <= th);
            unsigned ball = __ballot_sync(0xffffffffu, sel);
            if (lane == 0) red[wid] = __popc(ball);
            __syncthreads();
            int woff = 0;
            #pragma unroll
            for (int ww = 0; ww < 4; ww++) if (ww < wid) woff += red[ww];
            int tot = red[0] + red[1] + red[2] + red[3];
            int rank = wbase + woff + __popc(ball & ((1u << lane) - 1u));
            if (sel && rank < KMAX) g_idx[i * KMAX + rank] = q * 128 + t;
            wbase += tot;
            __syncthreads();
        }
        if (t == 0) g_cnt[i] = (wbase < KMAX) ? wbase : KMAX;
        __syncthreads();
    }
}

// ---------------------------------------------------------------------------
extern "C" void kernel_launch(void* const* d_in, const int* in_sizes, int n_in,
                              void* d_out, int out_size)
{
    const float* x      = (const float*)d_in[0];
    const float* pos    = (const float*)d_in[1];
    const float* nrm    = (const float*)d_in[2];
    // d_in[3] = batch (structured, unused)
    const float* w_lin  = (const float*)d_in[4];
    const float* w_src  = (const float*)d_in[5];
    const float* w_dst  = (const float*)d_in[6];
    const float* w_pos  = (const float*)d_in[7];
    const float* b_pos  = (const float*)d_in[8];
    const float* pos_g  = (const float*)d_in[9];
    const float* pos_b  = (const float*)d_in[10];
    const float* pos_m  = (const float*)d_in[11];
    const float* pos_v  = (const float*)d_in[12];
    const float* w_attn = (const float*)d_in[13];
    const float* b_attn = (const float*)d_in[14];
    const float* attn_g = (const float*)d_in[15];
    const float* attn_b = (const float*)d_in[16];
    const float* attn_m = (const float*)d_in[17];
    const float* attn_v = (const float*)d_in[18];
    float* out = (float*)d_out;

    cudaFuncSetAttribute(main_tc_kernel,
                         cudaFuncAttributeMaxDynamicSharedMemorySize, DYN_SIZE);
    cudaFuncSetAttribute(gemm3_tc_kernel,
                         cudaFuncAttributeMaxDynamicSharedMemorySize, G3_DYN);

    convert_w_kernel<<<192, 256>>>(w_lin, w_src, w_dst);
    gemm3_tc_kernel<<<128, 128, G3_DYN>>>(x);
    neigh_kernel<<<NPT / 4, 128>>>(pos);
    main_tc_kernel<<<GRID_MAIN, 256, DYN_SIZE>>>(
        pos, nrm, w_pos, b_pos, pos_g, pos_b, pos_m, pos_v,
        w_attn, b_attn, attn_g, attn_b, attn_m, attn_v, out);
}

// round 16
// speedup vs baseline: 3.4081x; 1.0593x over previous
#include <cuda_runtime.h>
#include <cuda_fp16.h>
#include <math.h>

#define NPT   8192
#define CC    128
#define PP    1024
#define KMAX  64
#define NPAIR (NPT/2)
#define GRID_MAIN 296

// ---- main kernel dynamic smem layout (byte offsets) ----
// A (fp16 MMA operand, swizzled 128x256B) overlaid by eS (fp16 alphas) after MMA.
// VD holds (V + delta) fp16. redS is DEDICATED (cross-half overlay of relS was
// the R12 NaN bug). All per-iteration regions are HALF-PRIVATE by row block.
#define OFF_A     0
#define OFF_B     32768
#define OFF_VD    65536
#define OFF_REL   98304
#define OFF_IDX   102400
#define OFF_WPF   102912
#define OFF_BP    105984
#define OFF_SA    106496
#define OFF_BA    107008
#define OFF_M     107520
#define OFF_RED   107648
#define DYN_SIZE  111744

// gemm3 dynamic smem (padded layout)
#define ASTR_B   272
#define G3_OFF_A 0
#define G3_OFF_W 17408
#define G3_DYN   52224

// scratch (device globals; zero-initialized at load; no allocations allowed)
__device__ float2 g_AV[NPT*CC];     // .x = x@w_src (Asrc), .y = x@w_lin (V)
__device__ float  g_Adst[NPT*CC];
__device__ int    g_idx[NPT*KMAX];
__device__ int    g_cnt[NPT];
__device__ __half g_WT3[3*CC*CC];   // [mat][n][k] fp16

// ---------------------------------------------------------------------------
__device__ __forceinline__ unsigned smem_u32(const void* p) {
    unsigned a;
    asm("{ .reg .u64 t; cvta.to.shared.u64 t, %1; cvt.u32.u64 %0, t; }" : "=r"(a) : "l"(p));
    return a;
}

__device__ __forceinline__ void ldsm4(unsigned* r, unsigned addr) {
    asm volatile("ldmatrix.sync.aligned.m8n8.x4.shared.b16 {%0,%1,%2,%3}, [%4];"
        : "=r"(r[0]), "=r"(r[1]), "=r"(r[2]), "=r"(r[3]) : "r"(addr));
}

__device__ __forceinline__ void mma16816(float* d, const unsigned* a, unsigned b0, unsigned b1) {
    asm volatile("mma.sync.aligned.m16n8k16.row.col.f32.f16.f16.f32 "
        "{%0,%1,%2,%3}, {%4,%5,%6,%7}, {%8,%9}, {%0,%1,%2,%3};"
        : "+f"(d[0]), "+f"(d[1]), "+f"(d[2]), "+f"(d[3])
        : "r"(a[0]), "r"(a[1]), "r"(a[2]), "r"(a[3]), "r"(b0), "r"(b1));
}

__device__ __forceinline__ float ex2f(float x) {
    float y;
    asm("ex2.approx.ftz.f32 %0, %1;" : "=f"(y) : "f"(x));
    return y;
}

// per-half barrier: 128 threads, barrier id 1 or 2
__device__ __forceinline__ void barh(int h) {
    asm volatile("bar.sync %0, %1;" :: "r"(h + 1), "r"(128) : "memory");
}

// fp16 tile addressing: 128 ch per 256B row, 16B-unit XOR swizzle.
__device__ __forceinline__ int haddr(int row, int ch) {
    return (row << 8) + ((((ch >> 3) ^ (row & 7)) & 15) << 4) + ((ch & 7) << 1);
}

// ---------------------------------------------------------------------------
__global__ __launch_bounds__(256)
void convert_w_kernel(const float* __restrict__ wl,
                      const float* __restrict__ ws,
                      const float* __restrict__ wd)
{
    int idx = blockIdx.x * 256 + threadIdx.x;
    if (idx >= 3 * CC * CC) return;
    int mat = idx >> 14;
    int n   = (idx >> 7) & 127;
    int k   = idx & 127;
    const float* W = (mat == 0) ? wl : (mat == 1) ? ws : wd;
    g_WT3[idx] = __float2half_rn(W[k * CC + n]);
}

// ---------------------------------------------------------------------------
// Kernel A: three GEMMs via HMMA. mat0 (w_lin) -> g_AV.y, mat1 (w_src) -> g_AV.x,
// mat2 (w_dst) -> g_Adst.
// ---------------------------------------------------------------------------
__global__ __launch_bounds__(128)
void gemm3_tc_kernel(const float* __restrict__ x)
{
    extern __shared__ __align__(16) char smem[];
    const unsigned sb = smem_u32(smem);
    const int t    = threadIdx.x;
    const int w    = t >> 5;
    const int lane = t & 31;
    const int row0 = blockIdx.x * 64;

    for (int q = t; q < 64 * CC; q += 128) {
        int row = q >> 7, c = q & 127;
        *(__half*)(smem + G3_OFF_A + row * ASTR_B + c * 2) =
            __float2half_rn(x[(size_t)(row0 + row) * CC + c]);
    }

    const unsigned aBase = sb + G3_OFF_A +
        (unsigned)((w * 16 + (lane & 15)) * ASTR_B + ((lane >> 4) << 4));
    const unsigned bBase = sb + G3_OFF_W +
        (unsigned)((((lane >> 4) << 3) + (lane & 7)) * ASTR_B + (((lane >> 3) & 1) << 4));

    for (int mat = 0; mat < 3; mat++) {
        const uint4* src = (const uint4*)(g_WT3 + mat * CC * CC);
        for (int q = t; q < CC * 16; q += 128) {
            int n = q >> 4, seg = q & 15;
            *(uint4*)(smem + G3_OFF_W + n * ASTR_B + seg * 16) = src[n * 16 + seg];
        }
        __syncthreads();

        float acc[16][4];
        #pragma unroll
        for (int nt = 0; nt < 16; nt++) {
            acc[nt][0] = 0.f; acc[nt][1] = 0.f; acc[nt][2] = 0.f; acc[nt][3] = 0.f;
        }
        #pragma unroll
        for (int kk = 0; kk < 8; kk++) {
            unsigned afr[4];
            ldsm4(afr, aBase + kk * 32);
            #pragma unroll
            for (int pp = 0; pp < 8; pp++) {
                unsigned bfr[4];
                ldsm4(bfr, bBase + (unsigned)(pp * 16 * ASTR_B) + kk * 32);
                mma16816(acc[2 * pp],     afr, bfr[0], bfr[1]);
                mma16816(acc[2 * pp + 1], afr, bfr[2], bfr[3]);
            }
        }

        int r0 = w * 16 + (lane >> 2);
        int c0 = 2 * (lane & 3);
        if (mat == 2) {
            #pragma unroll
            for (int nt = 0; nt < 16; nt++) {
                int col = nt * 8 + c0;
                *(float2*)&g_Adst[(size_t)(row0 + r0) * CC + col] =
                    make_float2(acc[nt][0], acc[nt][1]);
                *(float2*)&g_Adst[(size_t)(row0 + r0 + 8) * CC + col] =
                    make_float2(acc[nt][2], acc[nt][3]);
            }
        } else if (mat == 0) {
            #pragma unroll
            for (int nt = 0; nt < 16; nt++) {
                int col = nt * 8 + c0;
                size_t b0i = (size_t)(row0 + r0) * CC + col;
                size_t b1i = (size_t)(row0 + r0 + 8) * CC + col;
                g_AV[b0i].y     = acc[nt][0];
                g_AV[b0i + 1].y = acc[nt][1];
                g_AV[b1i].y     = acc[nt][2];
                g_AV[b1i + 1].y = acc[nt][3];
            }
        } else {
            #pragma unroll
            for (int nt = 0; nt < 16; nt++) {
                int col = nt * 8 + c0;
                size_t b0i = (size_t)(row0 + r0) * CC + col;
                size_t b1i = (size_t)(row0 + r0 + 8) * CC + col;
                g_AV[b0i].x     = acc[nt][0];
                g_AV[b0i + 1].x = acc[nt][1];
                g_AV[b1i].x     = acc[nt][2];
                g_AV[b1i + 1].x = acc[nt][3];
            }
        }
        __syncthreads();
    }
}

// ---------------------------------------------------------------------------
// Kernel C: HMMA fused attention. Persistent, 2 targets/iter, run as TWO
// independent half-CTA pipelines (128 threads each) with named barriers.
// ---------------------------------------------------------------------------
__global__ __launch_bounds__(256, 2)
void main_tc_kernel(const float* __restrict__ pos,
                    const float* __restrict__ nrm,
                    const float* __restrict__ w_pos,
                    const float* __restrict__ b_pos,
                    const float* __restrict__ pos_gamma,
                    const float* __restrict__ pos_beta,
                    const float* __restrict__ pos_mean,
                    const float* __restrict__ pos_var,
                    const float* __restrict__ w_attn,
                    const float* __restrict__ b_attn,
                    const float* __restrict__ attn_gamma,
                    const float* __restrict__ attn_beta,
                    const float* __restrict__ attn_mean,
                    const float* __restrict__ attn_var,
                    float* __restrict__ out)
{
    extern __shared__ __align__(16) char smem[];
    const unsigned sb = smem_u32(smem);

    const int t    = threadIdx.x;
    const int w    = t >> 5;
    const int lane = t & 31;
    const int hh   = t >> 7;      // half index (0/1) == target index within pair
    const int ht   = t & 127;     // thread id within half

    float* relS = (float*)(smem + OFF_REL);
    float* redS = (float*)(smem + OFF_RED);   // dedicated (NOT overlaid)
    int*   idxS = (int*)  (smem + OFF_IDX);   // premultiplied: gj * 128
    float* wpfS = (float*)(smem + OFF_WPF);
    float* bpS  = (float*)(smem + OFF_BP);
    float* saS  = (float*)(smem + OFF_SA);    // pre-scaled by log2(e)
    float* baS  = (float*)(smem + OFF_BA);    // pre-scaled by log2(e)
    int*   mS   = (int*)  (smem + OFF_M);

    // per-channel folded-BN constants
    if (t < 128) {
        int c = t;
        float sp = rsqrtf(pos_var[c] + 1e-5f) * pos_gamma[c];
        bpS[c] = (b_pos[c] - pos_mean[c]) * sp + pos_beta[c];
        #pragma unroll
        for (int r = 0; r < 6; r++) wpfS[r * 128 + c] = w_pos[r * 128 + c] * sp;
        const float L2E = 1.4426950408889634f;
        float sa = rsqrtf(attn_var[c] + 1e-5f) * attn_gamma[c];
        saS[c] = sa * L2E;
        baS[c] = ((b_attn[c] - attn_mean[c]) * sa + attn_beta[c]) * L2E;
    }

    // B[n][k] = w_attn[k][n] fp16 into swizzled tile (once per CTA)
    for (int q = t; q < 128 * 128; q += 256) {
        int n = q & 127, k = q >> 7;
        *(__half*)(smem + OFF_B + haddr(n, k)) = __float2half_rn(w_attn[k * 128 + n]);
    }
    __syncthreads();

    for (int p = blockIdx.x; p < NPAIR; p += GRID_MAIN) {
        const int i0 = 2 * p;
        const int i  = i0 + hh;          // this half's target
        barh(hh);   // prev-iter epilogue reads of this half's regions done

        // --- metadata (per half): part0 = idx+pos, part1 = nrm, 64 k each ---
        if (ht == 0) mS[hh] = g_cnt[i];
        {
            int kk   = ht & 63;
            int part = ht >> 6;
            int cb   = (i >> 10) << 10;
            int jj   = g_idx[i * KMAX + kk];   // stale/zero-init but always in-bounds
            int gj   = cb + jj;
            int k2   = hh * 64 + kk;
            if (part == 0) {
                idxS[k2] = gj * CC;
                relS[k2 * 8 + 0] = pos[i * 3 + 0] - pos[gj * 3 + 0];
                relS[k2 * 8 + 1] = pos[i * 3 + 1] - pos[gj * 3 + 1];
                relS[k2 * 8 + 2] = pos[i * 3 + 2] - pos[gj * 3 + 2];
            } else {
                relS[k2 * 8 + 3] = nrm[i * 3 + 0] - nrm[gj * 3 + 0];
                relS[k2 * 8 + 4] = nrm[i * 3 + 1] - nrm[gj * 3 + 1];
                relS[k2 * 8 + 5] = nrm[i * 3 + 2] - nrm[gj * 3 + 2];
            }
        }
        barh(hh);

        // --- build A (fp16, swizzled) + vdS = V + delta (fp16); one LDG.64/k ---
        {
            int c   = ht;                 // one channel per thread in this half
            int mt  = mS[hh];
            int tb  = hh * 64;
            float ad = g_Adst[i * CC + c];
            float bp = bpS[c];
            float wp0 = wpfS[0 * 128 + c], wp1 = wpfS[1 * 128 + c], wp2 = wpfS[2 * 128 + c];
            float wp3 = wpfS[3 * 128 + c], wp4 = wpfS[4 * 128 + c], wp5 = wpfS[5 * 128 + c];

            float2 buf[8];
            #pragma unroll
            for (int kp = 0; kp < 8; kp++)
                buf[kp] = (kp < mt) ? g_AV[idxS[tb + kp] + c] : make_float2(0.f, 0.f);

            int k = 0;
            #define A_BODY(KK, AV) do {                                           \
                const float4 ra = *(const float4*)&relS[(tb + (KK)) * 8];         \
                const float4 rb = *(const float4*)&relS[(tb + (KK)) * 8 + 4];     \
                float d = bp;                                                     \
                d = fmaf(ra.x, wp0, d); d = fmaf(ra.y, wp1, d);                   \
                d = fmaf(ra.z, wp2, d); d = fmaf(ra.w, wp3, d);                   \
                d = fmaf(rb.x, wp4, d); d = fmaf(rb.y, wp5, d);                   \
                d = fmaxf(d, 0.f);                                                \
                int ha = haddr(tb + (KK), c);                                     \
                *(__half*)(smem + OFF_VD + ha) = __float2half_rn((AV).y + d);     \
                *(__half*)(smem + OFF_A + ha) = __float2half_rn(ad - (AV).x + d); \
            } while (0)

            for (; k + 8 <= mt; k += 8) {
                #pragma unroll
                for (int j = 0; j < 8; j++) {
                    float2 av = buf[j];
                    buf[j] = (k + 8 + j < mt) ? g_AV[idxS[tb + k + 8 + j] + c]
                                              : make_float2(0.f, 0.f);
                    A_BODY(k + j, av);
                }
            }
            #pragma unroll
            for (int j = 0; j < 8; j++)
                if (k + j < mt) A_BODY(k + j, buf[j]);
            #undef A_BODY
        }
        barh(hh);

        // --- HMMA: warp w -> rows [w*16, w*16+16) x 128 couts; skip empty warps.
        // (w>>2 == hh for this half's warps; rows land in this half's 64-row block.)
        const int  wmt     = mS[hh];
        const bool wactive = ((w & 3) * 16) < wmt;

        if (wactive) {
            float acc[16][4];
            #pragma unroll
            for (int nt = 0; nt < 16; nt++) {
                acc[nt][0] = 0.f; acc[nt][1] = 0.f; acc[nt][2] = 0.f; acc[nt][3] = 0.f;
            }
            const int r    = w * 16 + (lane & 15);
            const int u0a  = lane >> 4;
            const int xr   = lane & 7;
            const unsigned aRow = sb + OFF_A + (unsigned)(r << 8);
            const int nrow0 = ((lane >> 4) << 3) + (lane & 7);
            const int u0b  = (lane >> 3) & 1;
            const unsigned bRow = sb + OFF_B + (unsigned)(nrow0 << 8);

            #pragma unroll
            for (int kk = 0; kk < 8; kk++) {
                unsigned afr[4];
                ldsm4(afr, aRow + (unsigned)((((kk * 2 + u0a) ^ xr) & 15) << 4));
                #pragma unroll
                for (int pp = 0; pp < 8; pp++) {
                    unsigned bfr[4];
                    ldsm4(bfr, bRow + (unsigned)(pp << 12)
                               + (unsigned)((((kk * 2 + u0b) ^ xr) & 15) << 4));
                    mma16816(acc[2 * pp],     afr, bfr[0], bfr[1]);
                    mma16816(acc[2 * pp + 1], afr, bfr[2], bfr[3]);
                }
            }

            // store alphas (pre-affine) fp16 into eS (overlay of this warp's A rows)
            int r0 = w * 16 + (lane >> 2);
            int c0 = 2 * (lane & 3);
            #pragma unroll
            for (int nt = 0; nt < 16; nt++) {
                int c = nt * 8 + c0;
                *(__half2*)(smem + OFF_A + haddr(r0, c)) =
                    __floats2half2_rn(acc[nt][0], acc[nt][1]);
                *(__half2*)(smem + OFF_A + haddr(r0 + 8, c)) =
                    __floats2half2_rn(acc[nt][2], acc[nt][3]);
            }
        }
        barh(hh);

        // --- epilogue (pure smem, per half): thread = (cp-pair, k-half) ---
        {
            const int half  = (ht >> 6) & 1;
            const int cpp   = ht & 63;
            const int cp    = cpp * 2;
            const int mt    = mS[hh];
            const int ibase = hh * 64;
            const int khalf = (mt + 1) >> 1;
            const int kb    = half ? khalf : 0;
            const int ke    = half ? mt : khalf;
            const float2 sa2 = *(const float2*)&saS[cp];
            const float2 ba2 = *(const float2*)&baS[cp];

            float fs0 = 0.f, fs1 = 0.f, fa0 = 0.f, fa1 = 0.f;

            #define E2_BODY(KK) do {                                              \
                int ha = haddr(ibase + (KK), cp);                                 \
                float2 ar = __half22float2(*(const __half2*)(smem + OFF_A + ha)); \
                float2 vd = __half22float2(*(const __half2*)(smem + OFF_VD + ha)); \
                float a0 = fmaxf(fmaf(ar.x, sa2.x, ba2.x), 0.f);                  \
                float a1 = fmaxf(fmaf(ar.y, sa2.y, ba2.y), 0.f);                  \
                float e0 = ex2f(a0);                                              \
                float e1 = ex2f(a1);                                              \
                fs0 += e0; fs1 += e1;                                             \
                fa0 = fmaf(e0, vd.x, fa0);                                        \
                fa1 = fmaf(e1, vd.y, fa1);                                        \
            } while (0)

            int k = kb;
            for (; k + 4 <= ke; k += 4) {
                E2_BODY(k); E2_BODY(k + 1); E2_BODY(k + 2); E2_BODY(k + 3);
            }
            for (; k < ke; k++) E2_BODY(k);
            #undef E2_BODY

            *(float4*)&redS[(((half << 1) | hh) * 64 + cpp) * 4] =
                make_float4(fs0, fs1, fa0, fa1);
        }
        barh(hh);

        // --- final (per half): merge the two k-halves, normalize, write out ---
        {
            int cp2 = ht;
            int cq  = cp2 >> 1, s = cp2 & 1;
            const float* r0 = &redS[(hh * 64 + cq) * 4];
            const float* r1 = &redS[((2 + hh) * 64 + cq) * 4];
            float fs = r0[s] + r1[s];
            float fa = r0[2 + s] + r1[2 + s];
            out[(size_t)i * CC + cp2] = fa / fs;
        }
    }
}

// ---------------------------------------------------------------------------
// Kernel B: radius + nearest-K selection (smem-staged cloud)
// ---------------------------------------------------------------------------
__global__ __launch_bounds__(128)
void neigh_kernel(const float* __restrict__ pos)
{
    const int t     = threadIdx.x;
    const int lane  = t & 31;
    const int wid   = t >> 5;
    const int i0    = blockIdx.x * 4;
    const int cbase = (i0 >> 10) << 10;

    __shared__ float pos_s[PP * 3];
    __shared__ int   red[4];

    for (int idx = t; idx < PP * 3; idx += 128)
        pos_s[idx] = pos[cbase * 3 + idx];
    __syncthreads();

    const unsigned R2b = __float_as_uint(0.04f);

    for (int tt = 0; tt < 4; tt++) {
        const int i  = i0 + tt;
        const int li = i - cbase;
        const float px = pos_s[li * 3 + 0];
        const float py = pos_s[li * 3 + 1];
        const float pz = pos_s[li * 3 + 2];

        unsigned bits[8];
        #pragma unroll
        for (int q = 0; q < 8; q++) {
            int j = q * 128 + t;
            float dx = px - pos_s[j * 3 + 0];
            float dy = py - pos_s[j * 3 + 1];
            float dz = pz - pos_s[j * 3 + 2];
            float d2 = dx * dx + dy * dy + dz * dz;
            bits[q] = __float_as_uint(d2);
        }

        int local = 0;
        #pragma unroll
        for (int q = 0; q < 8; q++) local += (bits[q] <= R2b);
        #pragma unroll
        for (int o = 16; o > 0; o >>= 1) local += __shfl_down_sync(0xffffffffu, local, o);
        if (lane == 0) red[wid] = local;
        __syncthreads();
        int total = red[0] + red[1] + red[2] + red[3];
        __syncthreads();

        unsigned th = R2b;
        if (total > KMAX) {
            unsigned lo = 0, hi = R2b;
            while (lo < hi) {
                unsigned mid = lo + ((hi - lo) >> 1);
                int cnt = 0;
                #pragma unroll
                for (int q = 0; q < 8; q++) cnt += (bits[q] <= mid);
                #pragma unroll
                for (int o = 16; o > 0; o >>= 1) cnt += __shfl_down_sync(0xffffffffu, cnt, o);
                if (lane == 0) red[wid] = cnt;
                __syncthreads();
                int tot = red[0] + red[1] + red[2] + red[3];
                __syncthreads();
                if (tot >= KMAX) hi = mid; else lo = mid + 1;
            }
            th = lo;
        }

        int wbase = 0;
        for (int q = 0; q < 8; q++) {
            bool sel = (bits[q] <= th);
            unsigned ball = __ballot_sync(0xffffffffu, sel);
            if (lane == 0) red[wid] = __popc(ball);
            __syncthreads();
            int woff = 0;
            #pragma unroll
            for (int ww = 0; ww < 4; ww++) if (ww < wid) woff += red[ww];
            int tot = red[0] + red[1] + red[2] + red[3];
            int rank = wbase + woff + __popc(ball & ((1u << lane) - 1u));
            if (sel && rank < KMAX) g_idx[i * KMAX + rank] = q * 128 + t;
            wbase += tot;
            __syncthreads();
        }
        if (t == 0) g_cnt[i] = (wbase < KMAX) ? wbase : KMAX;
        __syncthreads();
    }
}

// ---------------------------------------------------------------------------
extern "C" void kernel_launch(void* const* d_in, const int* in_sizes, int n_in,
                              void* d_out, int out_size)
{
    const float* x      = (const float*)d_in[0];
    const float* pos    = (const float*)d_in[1];
    const float* nrm    = (const float*)d_in[2];
    // d_in[3] = batch (structured, unused)
    const float* w_lin  = (const float*)d_in[4];
    const float* w_src  = (const float*)d_in[5];
    const float* w_dst  = (const float*)d_in[6];
    const float* w_pos  = (const float*)d_in[7];
    const float* b_pos  = (const float*)d_in[8];
    const float* pos_g  = (const float*)d_in[9];
    const float* pos_b  = (const float*)d_in[10];
    const float* pos_m  = (const float*)d_in[11];
    const float* pos_v  = (const float*)d_in[12];
    const float* w_attn = (const float*)d_in[13];
    const float* b_attn = (const float*)d_in[14];
    const float* attn_g = (const float*)d_in[15];
    const float* attn_b = (const float*)d_in[16];
    const float* attn_m = (const float*)d_in[17];
    const float* attn_v = (const float*)d_in[18];
    float* out = (float*)d_out;

    cudaFuncSetAttribute(main_tc_kernel,
                         cudaFuncAttributeMaxDynamicSharedMemorySize, DYN_SIZE);
    cudaFuncSetAttribute(gemm3_tc_kernel,
                         cudaFuncAttributeMaxDynamicSharedMemorySize, G3_DYN);

    convert_w_kernel<<<192, 256>>>(w_lin, w_src, w_dst);
    gemm3_tc_kernel<<<128, 128, G3_DYN>>>(x);
    neigh_kernel<<<NPT / 4, 128>>>(pos);
    main_tc_kernel<<<GRID_MAIN, 256, DYN_SIZE>>>(
        pos, nrm, w_pos, b_pos, pos_g, pos_b, pos_m, pos_v,
        w_attn, b_attn, attn_g, attn_b, attn_m, attn_v, out);
}